// round 2
// baseline (speedup 1.0000x reference)
#include <cuda_runtime.h>
#include <math.h>

#define NN 20000
#define EE 200000
#define HD 256
#define NHEADS 4
#define NDIM 128
#define EDIM 64
#define NL 3

// ---------------- scratch (static device globals; no runtime allocation) ----------------
__device__ float g_x  [(size_t)NN * HD];
__device__ float g_x2 [(size_t)NN * HD];
__device__ float g_xp [(size_t)NN * NHEADS * HD];   // [N, 4, 256] = [N,1024]
__device__ float g_as [NN * NHEADS];
__device__ float g_ad [NN * NHEADS];
__device__ float g_ew [EE];
__device__ float g_loopw[NN];
__device__ int   g_counts[NN];
__device__ int   g_cursor[NN];
__device__ int   g_rowptr[NN + 1];
__device__ int   g_csrc[EE];
__device__ int   g_ceid[EE];
__device__ float g_hmid[4 * (size_t)NN * (HD / 2)];
__device__ float g_wmean[NL * EDIM];
__device__ float g_bmean[NL];
__device__ float g_cvec [NL * NHEADS];

// ---------------- small preprocessing kernels ----------------
__global__ void k_zero() {
    int i = blockIdx.x * 256 + threadIdx.x;
    if (i < NN) { g_counts[i] = 0; g_cursor[i] = 0; }
}

__global__ void k_count(const int* __restrict__ dst) {
    int e = blockIdx.x * 256 + threadIdx.x;
    if (e < EE) atomicAdd(&g_counts[dst[e]], 1);
}

// single-block inclusive scan -> row_ptr
__global__ void k_scan() {
    __shared__ int sh[1024];
    int tid = threadIdx.x;
    int carry = 0;
    for (int base = 0; base < NN; base += 1024) {
        int i = base + tid;
        int v = (i < NN) ? g_counts[i] : 0;
        sh[tid] = v;
        __syncthreads();
        for (int off = 1; off < 1024; off <<= 1) {
            int t = (tid >= off) ? sh[tid - off] : 0;
            __syncthreads();
            sh[tid] += t;
            __syncthreads();
        }
        if (i < NN) g_rowptr[i + 1] = carry + sh[tid];
        carry += sh[1023];
        __syncthreads();
    }
    if (tid == 0) g_rowptr[0] = 0;
}

__global__ void k_scatter(const int* __restrict__ src, const int* __restrict__ dst) {
    int e = blockIdx.x * 256 + threadIdx.x;
    if (e < EE) {
        int d = dst[e];
        int pos = g_rowptr[d] + atomicAdd(&g_cursor[d], 1);
        g_csrc[pos] = src[e];
        g_ceid[pos] = e;
    }
}

// wmean[l*64+d] = mean over 256 cols of edge_enc_w[l,d,:]
__global__ void k_wmean(const float* __restrict__ W) {
    __shared__ float red[256];
    int ld = blockIdx.x;  // 0..191
    red[threadIdx.x] = W[(size_t)ld * 256 + threadIdx.x];
    __syncthreads();
    for (int s = 128; s; s >>= 1) {
        if (threadIdx.x < s) red[threadIdx.x] += red[threadIdx.x + s];
        __syncthreads();
    }
    if (threadIdx.x == 0) g_wmean[ld] = red[0] * (1.f / 256.f);
}

__global__ void k_bmean(const float* __restrict__ b) {
    __shared__ float red[256];
    int l = blockIdx.x;
    red[threadIdx.x] = b[l * 256 + threadIdx.x];
    __syncthreads();
    for (int s = 128; s; s >>= 1) {
        if (threadIdx.x < s) red[threadIdx.x] += red[threadIdx.x + s];
        __syncthreads();
    }
    if (threadIdx.x == 0) g_bmean[l] = red[0] * (1.f / 256.f);
}

// c[l,h] = sum_d lin_edge_w[l,0,h*256+d] * att_edge[l,h,d]
__global__ void k_cvec(const float* __restrict__ lew, const float* __restrict__ ae) {
    __shared__ float red[256];
    int lh = blockIdx.x;  // 0..11
    size_t off = (size_t)lh * 256 + threadIdx.x;
    red[threadIdx.x] = lew[off] * ae[off];
    __syncthreads();
    for (int s = 128; s; s >>= 1) {
        if (threadIdx.x < s) red[threadIdx.x] += red[threadIdx.x + s];
        __syncthreads();
    }
    if (threadIdx.x == 0) g_cvec[lh] = red[0];
}

// ew[e] = edge_attr[e,:] . wmean[l,:] + bmean[l]   (warp per edge)
__global__ void k_ew(const float* __restrict__ ea, int l) {
    int warp = threadIdx.x >> 5, lane = threadIdx.x & 31;
    int e = blockIdx.x * 8 + warp;
    if (e >= EE) return;
    const float* row = ea + (size_t)e * EDIM;
    const float* wm = g_wmean + l * EDIM;
    float s = 0.f;
    for (int i = lane; i < EDIM; i += 32) s += row[i] * wm[i];
    for (int o = 16; o; o >>= 1) s += __shfl_down_sync(0xffffffff, s, o);
    if (lane == 0) g_ew[e] = s + g_bmean[l];
}

__global__ void k_loopw() {
    int n = blockIdx.x * 256 + threadIdx.x;
    if (n < NN) {
        int b = g_rowptr[n], e = g_rowptr[n + 1];
        float s = 0.f;
        for (int p = b; p < e; p++) s += g_ew[g_ceid[p]];
        float dg = (float)(e - b);
        g_loopw[n] = s / fmaxf(dg, 1.f);
    }
}

// ---------------- SGEMM: C[M,N] = A[M,K] @ B[K,N] (+bias)(+relu) ----------------
// classic 128x128x8, 256 threads, 8x8 per-thread microtile. N,K multiples of 8/128.
#define BM 128
#define BN 128
#define BK 8
__global__ __launch_bounds__(256) void k_sgemm(const float* __restrict__ A,
                                               const float* __restrict__ B,
                                               float* __restrict__ C,
                                               int M, int N, int K,
                                               const float* __restrict__ bias,
                                               int doRelu) {
    __shared__ float As[BK][BM];
    __shared__ float Bs[BK][BN];
    int tid = threadIdx.x;
    int brow = blockIdx.y, bcol = blockIdx.x;

    int aRow = tid >> 1;
    int aCol = (tid & 1) * 4;
    int bRow = tid >> 5;
    int bCol = (tid & 31) * 4;

    const float* Ab = A + (size_t)brow * BM * K;
    const float* Bb = B + (size_t)bcol * BN;

    float acc[8][8];
#pragma unroll
    for (int i = 0; i < 8; i++)
#pragma unroll
        for (int j = 0; j < 8; j++) acc[i][j] = 0.f;

    int tr = (tid / 16) * 8;
    int tc = (tid % 16) * 8;
    int gRowA = brow * BM + aRow;

    for (int k0 = 0; k0 < K; k0 += BK) {
        float4 av;
        if (gRowA < M)
            av = *(const float4*)(Ab + (size_t)aRow * K + k0 + aCol);
        else
            av = make_float4(0.f, 0.f, 0.f, 0.f);
        As[aCol + 0][aRow] = av.x;
        As[aCol + 1][aRow] = av.y;
        As[aCol + 2][aRow] = av.z;
        As[aCol + 3][aRow] = av.w;

        float4 bv = *(const float4*)(Bb + (size_t)(k0 + bRow) * N + bCol);
        *(float4*)&Bs[bRow][bCol] = bv;
        __syncthreads();

#pragma unroll
        for (int kk = 0; kk < BK; kk++) {
            float ar[8], br[8];
#pragma unroll
            for (int i = 0; i < 8; i++) ar[i] = As[kk][tr + i];
#pragma unroll
            for (int j = 0; j < 8; j++) br[j] = Bs[kk][tc + j];
#pragma unroll
            for (int i = 0; i < 8; i++)
#pragma unroll
                for (int j = 0; j < 8; j++) acc[i][j] = fmaf(ar[i], br[j], acc[i][j]);
        }
        __syncthreads();
    }

#pragma unroll
    for (int i = 0; i < 8; i++) {
        int r = brow * BM + tr + i;
        if (r < M) {
#pragma unroll
            for (int j = 0; j < 8; j++) {
                int cn = bcol * BN + tc + j;
                float v = acc[i][j];
                if (bias) v += bias[cn];
                if (doRelu) v = fmaxf(v, 0.f);
                C[(size_t)r * N + cn] = v;
            }
        }
    }
}

// ---------------- attention scores: a_s[n,h], a_d[n,h] from xp ----------------
__global__ void k_attn(const float* __restrict__ att_s, const float* __restrict__ att_d) {
    int n = blockIdx.x;
    int warp = threadIdx.x >> 5, lane = threadIdx.x & 31;  // blockDim = 128: 4 warps = 4 heads
    const float* xr = g_xp + (size_t)n * 1024 + warp * 256;
    const float* as = att_s + warp * 256;
    const float* ad = att_d + warp * 256;
    float s = 0.f, d = 0.f;
    for (int i = lane; i < 256; i += 32) {
        float v = xr[i];
        s += v * as[i];
        d += v * ad[i];
    }
    for (int o = 16; o; o >>= 1) {
        s += __shfl_down_sync(0xffffffff, s, o);
        d += __shfl_down_sync(0xffffffff, d, o);
    }
    if (lane == 0) {
        g_as[n * 4 + warp] = s;
        g_ad[n * 4 + warp] = d;
    }
}

// ---------------- fused GAT layer: softmax + aggregate + bias + LN + residual relu ----------------
__device__ __forceinline__ float lrelu(float x) { return fmaxf(x, 0.2f * x); }

#define CH 64
__global__ __launch_bounds__(256) void k_gat(const float* __restrict__ x,
                                             float* __restrict__ xo,
                                             int l,
                                             const float* __restrict__ gat_b,
                                             const float* __restrict__ ln_g,
                                             const float* __restrict__ ln_b) {
    int n = blockIdx.x, tid = threadIdx.x;
    __shared__ float4 red[256];
    __shared__ float wt[CH][4];
    __shared__ int ssrc[CH];
    __shared__ float4 sM, sInv;
    __shared__ float sMu, sVar;

    int beg = g_rowptr[n];
    int deg = g_rowptr[n + 1] - beg;
    int total = deg + 1;

    float c0 = g_cvec[l * 4 + 0], c1 = g_cvec[l * 4 + 1];
    float c2 = g_cvec[l * 4 + 2], c3 = g_cvec[l * 4 + 3];
    float ad0 = g_ad[n * 4 + 0], ad1 = g_ad[n * 4 + 1];
    float ad2 = g_ad[n * 4 + 2], ad3 = g_ad[n * 4 + 3];
    float lw = g_loopw[n];

    // pass 1: per-head max
    float4 lm = make_float4(-1e30f, -1e30f, -1e30f, -1e30f);
    for (int i = tid; i < total; i += 256) {
        int s; float w;
        if (i < deg) { int p = beg + i; s = g_csrc[p]; w = g_ew[g_ceid[p]]; }
        else { s = n; w = lw; }
        float l0 = lrelu(g_as[s * 4 + 0] + ad0 + w * c0);
        float l1 = lrelu(g_as[s * 4 + 1] + ad1 + w * c1);
        float l2 = lrelu(g_as[s * 4 + 2] + ad2 + w * c2);
        float l3 = lrelu(g_as[s * 4 + 3] + ad3 + w * c3);
        lm.x = fmaxf(lm.x, l0); lm.y = fmaxf(lm.y, l1);
        lm.z = fmaxf(lm.z, l2); lm.w = fmaxf(lm.w, l3);
    }
    red[tid] = lm;
    __syncthreads();
    for (int s = 128; s; s >>= 1) {
        if (tid < s) {
            float4 a = red[tid], b = red[tid + s];
            a.x = fmaxf(a.x, b.x); a.y = fmaxf(a.y, b.y);
            a.z = fmaxf(a.z, b.z); a.w = fmaxf(a.w, b.w);
            red[tid] = a;
        }
        __syncthreads();
    }
    if (tid == 0) sM = red[0];
    __syncthreads();
    float4 m = sM;
    __syncthreads();

    // pass 2: per-head sum of exp
    float4 ls = make_float4(0.f, 0.f, 0.f, 0.f);
    for (int i = tid; i < total; i += 256) {
        int s; float w;
        if (i < deg) { int p = beg + i; s = g_csrc[p]; w = g_ew[g_ceid[p]]; }
        else { s = n; w = lw; }
        ls.x += expf(lrelu(g_as[s * 4 + 0] + ad0 + w * c0) - m.x);
        ls.y += expf(lrelu(g_as[s * 4 + 1] + ad1 + w * c1) - m.y);
        ls.z += expf(lrelu(g_as[s * 4 + 2] + ad2 + w * c2) - m.z);
        ls.w += expf(lrelu(g_as[s * 4 + 3] + ad3 + w * c3) - m.w);
    }
    red[tid] = ls;
    __syncthreads();
    for (int s = 128; s; s >>= 1) {
        if (tid < s) {
            float4 a = red[tid], b = red[tid + s];
            a.x += b.x; a.y += b.y; a.z += b.z; a.w += b.w;
            red[tid] = a;
        }
        __syncthreads();
    }
    if (tid == 0) {
        float4 t = red[0];
        sInv = make_float4(0.25f / t.x, 0.25f / t.y, 0.25f / t.z, 0.25f / t.w);
    }
    __syncthreads();
    float4 inv = sInv;

    // pass 3: chunked weight compute + gather-accumulate (thread tid owns feature d=tid)
    float acc = 0.f;
    for (int ch = 0; ch < total; ch += CH) {
        int cnt = min(CH, total - ch);
        __syncthreads();
        if (tid < cnt) {
            int i = ch + tid;
            int s; float w;
            if (i < deg) { int p = beg + i; s = g_csrc[p]; w = g_ew[g_ceid[p]]; }
            else { s = n; w = lw; }
            wt[tid][0] = expf(lrelu(g_as[s * 4 + 0] + ad0 + w * c0) - m.x) * inv.x;
            wt[tid][1] = expf(lrelu(g_as[s * 4 + 1] + ad1 + w * c1) - m.y) * inv.y;
            wt[tid][2] = expf(lrelu(g_as[s * 4 + 2] + ad2 + w * c2) - m.z) * inv.z;
            wt[tid][3] = expf(lrelu(g_as[s * 4 + 3] + ad3 + w * c3) - m.w) * inv.w;
            ssrc[tid] = s;
        }
        __syncthreads();
        for (int j = 0; j < cnt; j++) {
            const float* xr = g_xp + (size_t)ssrc[j] * 1024;
            acc += wt[j][0] * xr[tid] + wt[j][1] * xr[256 + tid] +
                   wt[j][2] * xr[512 + tid] + wt[j][3] * xr[768 + tid];
        }
    }

    float h = acc + gat_b[tid];

    // layernorm over 256 features (reuse red.x as float scratch)
    float* redf = (float*)red;
    __syncthreads();
    redf[tid] = h;
    __syncthreads();
    for (int s = 128; s; s >>= 1) {
        if (tid < s) redf[tid] += redf[tid + s];
        __syncthreads();
    }
    if (tid == 0) sMu = redf[0] * (1.f / 256.f);
    __syncthreads();
    float mu = sMu;
    float df = h - mu;
    __syncthreads();
    redf[tid] = df * df;
    __syncthreads();
    for (int s = 128; s; s >>= 1) {
        if (tid < s) redf[tid] += redf[tid + s];
        __syncthreads();
    }
    if (tid == 0) sVar = redf[0] * (1.f / 256.f);
    __syncthreads();
    float var = sVar;

    float y = ln_g[tid] * df * rsqrtf(var + 1e-5f) + ln_b[tid];
    size_t idx = (size_t)n * 256 + tid;
    xo[idx] = fmaxf(x[idx] + y, 0.f);
}

// ---------------- prediction heads epilogue ----------------
__global__ void k_headout(const float* __restrict__ w2, const float* __restrict__ b2,
                          float* __restrict__ out) {
    int n = blockIdx.x;
    int k = threadIdx.x >> 5, lane = threadIdx.x & 31;  // blockDim = 128
    const float* hr = g_hmid + ((size_t)k * NN + n) * 128;
    const float* w = w2 + k * 128;
    float s = 0.f;
    for (int i = lane; i < 128; i += 32) s += hr[i] * w[i];
    for (int o = 16; o; o >>= 1) s += __shfl_down_sync(0xffffffff, s, o);
    if (lane == 0) {
        float v = s + b2[k];
        if (k == 0 || k == 3) v = 1.f / (1.f + expf(-v));
        out[(size_t)k * NN + n] = v;
    }
}

__global__ void k_emb(const float* __restrict__ emb, float* __restrict__ out) {
    size_t i = (size_t)blockIdx.x * 256 + threadIdx.x;
    if (i < (size_t)NN * HD) out[(size_t)4 * NN + i] = emb[i];
}

// ---------------- launch ----------------
extern "C" void kernel_launch(void* const* d_in, const int* in_sizes, int n_in,
                              void* d_out, int out_size) {
    const float* node_features = (const float*)d_in[0];
    const float* edge_attr     = (const float*)d_in[1];
    const float* enc_w         = (const float*)d_in[2];
    const float* enc_b         = (const float*)d_in[3];
    const float* edge_enc_w    = (const float*)d_in[4];
    const float* edge_enc_b    = (const float*)d_in[5];
    const float* gat_w         = (const float*)d_in[6];
    const float* att_src       = (const float*)d_in[7];
    const float* att_dst       = (const float*)d_in[8];
    const float* att_edge      = (const float*)d_in[9];
    const float* lin_edge_w    = (const float*)d_in[10];
    const float* gat_b         = (const float*)d_in[11];
    const float* ln_g          = (const float*)d_in[12];
    const float* ln_b          = (const float*)d_in[13];
    const float* head_w1       = (const float*)d_in[14];
    const float* head_b1       = (const float*)d_in[15];
    const float* head_w2       = (const float*)d_in[16];
    const float* head_b2       = (const float*)d_in[17];
    const int*   src           = (const int*)d_in[18];
    const int*   dst           = src + EE;
    float* out = (float*)d_out;

    float *px, *px2, *pxp, *phmid;
    cudaGetSymbolAddress((void**)&px, g_x);
    cudaGetSymbolAddress((void**)&px2, g_x2);
    cudaGetSymbolAddress((void**)&pxp, g_xp);
    cudaGetSymbolAddress((void**)&phmid, g_hmid);

    // ---- graph preprocessing (dst-CSR) + per-layer constants ----
    k_zero<<<(NN + 255) / 256, 256>>>();
    k_count<<<(EE + 255) / 256, 256>>>(dst);
    k_scan<<<1, 1024>>>();
    k_scatter<<<(EE + 255) / 256, 256>>>(src, dst);
    k_wmean<<<NL * EDIM, 256>>>(edge_enc_w);
    k_bmean<<<NL, 256>>>(edge_enc_b);
    k_cvec<<<NL * NHEADS, 256>>>(lin_edge_w, att_edge);

    // ---- encoder: x = relu(nf @ enc_w + enc_b) ----
    k_sgemm<<<dim3(HD / BN, (NN + BM - 1) / BM), 256>>>(
        node_features, enc_w, px, NN, HD, NDIM, enc_b, 1);

    // ---- 3 GAT layers ----
    for (int l = 0; l < NL; l++) {
        const float* A = (l & 1) ? px2 : px;
        float* XO      = (l & 1) ? px  : px2;

        // xp = x @ gat_w[l]   [20000,256] @ [256,1024]
        k_sgemm<<<dim3(1024 / BN, (NN + BM - 1) / BM), 256>>>(
            A, gat_w + (size_t)l * 256 * 1024, pxp, NN, 1024, 256, nullptr, 0);

        k_attn<<<NN, 128>>>(att_src + l * 1024, att_dst + l * 1024);
        k_ew<<<(EE + 7) / 8, 256>>>(edge_attr, l);
        k_loopw<<<(NN + 255) / 256, 256>>>();
        k_gat<<<NN, 256>>>(A, XO, l, gat_b + l * 256, ln_g + l * 256, ln_b + l * 256);
    }
    // after l=2, emb lives in px2

    // ---- 4 prediction heads ----
    for (int k = 0; k < 4; k++) {
        k_sgemm<<<dim3(128 / BN, (NN + BM - 1) / BM), 256>>>(
            px2, head_w1 + (size_t)k * 256 * 128, phmid + (size_t)k * NN * 128,
            NN, 128, 256, head_b1 + k * 128, 1);
    }
    k_headout<<<NN, 128>>>(head_w2, head_b2, out);
    if (out_size >= 4 * NN + NN * HD)
        k_emb<<<((size_t)NN * HD + 255) / 256, 256>>>(px2, out);
}

// round 4
// speedup vs baseline: 1.4631x; 1.4631x over previous
#include <cuda_runtime.h>
#include <cuda_bf16.h>
#include <cstdint>
#include <math.h>

#define NN 20000
#define EE 200000
#define HD 256
#define NHEADS 4
#define NDIM 128
#define EDIM 64
#define NL 3

// ---------------- scratch (static device globals; no runtime allocation) ----------------
__device__ float g_x  [(size_t)NN * HD];
__device__ float g_x2 [(size_t)NN * HD];
__device__ float g_xp [(size_t)NN * NHEADS * HD];   // [N, 4, 256] = [N,1024]
__device__ float g_as [NN * NHEADS];
__device__ float g_ad [NN * NHEADS];
__device__ float g_ew [EE];
__device__ float g_loopw[NN];
__device__ int   g_counts[NN];
__device__ int   g_cursor[NN];
__device__ int   g_rowptr[NN + 1];
__device__ int   g_csrc[EE];
__device__ int   g_ceid[EE];
__device__ float g_hmid[4 * (size_t)NN * (HD / 2)];
__device__ float g_wmean[NL * EDIM];
__device__ float g_bmean[NL];
__device__ float g_cvec [NL * NHEADS];
// bf16 split buffers for tensor-core GEMM
__device__ __nv_bfloat16 g_Ah[(size_t)NN * HD];
__device__ __nv_bfloat16 g_Al[(size_t)NN * HD];
__device__ __nv_bfloat16 g_Bh[1024 * 256];
__device__ __nv_bfloat16 g_Bl[1024 * 256];

// ---------------- warp-level bf16 MMA (HMMA path; legal on compute_103 base target) ----------------
__device__ __forceinline__ void mma16816(float* c, const uint32_t* a, const uint32_t* b) {
    asm volatile(
        "mma.sync.aligned.m16n8k16.row.col.f32.bf16.bf16.f32 "
        "{%0,%1,%2,%3}, {%4,%5,%6,%7}, {%8,%9}, {%0,%1,%2,%3};"
        : "+f"(c[0]), "+f"(c[1]), "+f"(c[2]), "+f"(c[3])
        : "r"(a[0]), "r"(a[1]), "r"(a[2]), "r"(a[3]), "r"(b[0]), "r"(b[1]));
}

// ---------------- bf16x3 GEMM: C[M,N] = A[M,K]@B[K,N] (+bias)(+relu) ----------------
// A as bf16 hi/lo [M,K] row-major; B pre-transposed+split as [N,K] row-major (K-contiguous).
// Block tile 128x128, 8 warps (2Mx4N), warp tile 64x32, K-chunk 64.
#define KCH 64
#define AST 72                         // smem row stride in bf16 (conflict-free fragment LDS)
#define GEMM_SMEM (4 * 128 * AST * 2)  // 73728 bytes
__global__ __launch_bounds__(256) void k_mma(
    const __nv_bfloat16* __restrict__ Ah, const __nv_bfloat16* __restrict__ Al,
    const __nv_bfloat16* __restrict__ Bh, const __nv_bfloat16* __restrict__ Bl,
    float* __restrict__ C, int M, int N, int K,
    const float* __restrict__ bias, int doRelu) {
    extern __shared__ __nv_bfloat16 sm[];
    __nv_bfloat16* sAh = sm;
    __nv_bfloat16* sAl = sm + 128 * AST;
    __nv_bfloat16* sBh = sm + 2 * 128 * AST;
    __nv_bfloat16* sBl = sm + 3 * 128 * AST;

    int tid = threadIdx.x, lane = tid & 31, wid = tid >> 5;
    int nb = blockIdx.x, mb = blockIdx.y;
    int warpM = wid >> 2, warpN = wid & 3;
    int gid = lane >> 2, qid = lane & 3;

    float acc[4][4][4];
#pragma unroll
    for (int i = 0; i < 4; i++)
#pragma unroll
        for (int j = 0; j < 4; j++)
#pragma unroll
            for (int k = 0; k < 4; k++) acc[i][j][k] = 0.f;

    for (int kc = 0; kc < K; kc += KCH) {
        // A chunk: 128 rows x 64 bf16 (hi+lo)
#pragma unroll
        for (int i = tid; i < 1024; i += 256) {
            int row = i >> 3, c = i & 7;
            int gr = mb * 128 + row;
            int4 vh = make_int4(0, 0, 0, 0), vl = vh;
            if (gr < M) {
                vh = *(const int4*)(Ah + (size_t)gr * K + kc + c * 8);
                vl = *(const int4*)(Al + (size_t)gr * K + kc + c * 8);
            }
            *(int4*)(sAh + row * AST + c * 8) = vh;
            *(int4*)(sAl + row * AST + c * 8) = vl;
        }
        // B chunk: 128 n-rows x 64 bf16 (hi+lo); N is always a multiple of 128
#pragma unroll
        for (int i = tid; i < 1024; i += 256) {
            int row = i >> 3, c = i & 7;
            int gn = nb * 128 + row;
            *(int4*)(sBh + row * AST + c * 8) = *(const int4*)(Bh + (size_t)gn * K + kc + c * 8);
            *(int4*)(sBl + row * AST + c * 8) = *(const int4*)(Bl + (size_t)gn * K + kc + c * 8);
        }
        __syncthreads();

#pragma unroll
        for (int ks = 0; ks < KCH; ks += 16) {
            uint32_t ah[4][4], al[4][4], bh[4][2], bl[4][2];
#pragma unroll
            for (int mt = 0; mt < 4; mt++) {
                const __nv_bfloat16* baseH = sAh + (warpM * 64 + mt * 16 + gid) * AST + ks + qid * 2;
                const __nv_bfloat16* baseL = sAl + (warpM * 64 + mt * 16 + gid) * AST + ks + qid * 2;
                ah[mt][0] = *(const uint32_t*)(baseH);
                ah[mt][1] = *(const uint32_t*)(baseH + 8 * AST);
                ah[mt][2] = *(const uint32_t*)(baseH + 8);
                ah[mt][3] = *(const uint32_t*)(baseH + 8 * AST + 8);
                al[mt][0] = *(const uint32_t*)(baseL);
                al[mt][1] = *(const uint32_t*)(baseL + 8 * AST);
                al[mt][2] = *(const uint32_t*)(baseL + 8);
                al[mt][3] = *(const uint32_t*)(baseL + 8 * AST + 8);
            }
#pragma unroll
            for (int nt = 0; nt < 4; nt++) {
                const __nv_bfloat16* baseH = sBh + (warpN * 32 + nt * 8 + gid) * AST + ks + qid * 2;
                const __nv_bfloat16* baseL = sBl + (warpN * 32 + nt * 8 + gid) * AST + ks + qid * 2;
                bh[nt][0] = *(const uint32_t*)(baseH);
                bh[nt][1] = *(const uint32_t*)(baseH + 8);
                bl[nt][0] = *(const uint32_t*)(baseL);
                bl[nt][1] = *(const uint32_t*)(baseL + 8);
            }
#pragma unroll
            for (int mt = 0; mt < 4; mt++)
#pragma unroll
                for (int nt = 0; nt < 4; nt++) {
                    mma16816(acc[mt][nt], ah[mt], bh[nt]);
                    mma16816(acc[mt][nt], ah[mt], bl[nt]);
                    mma16816(acc[mt][nt], al[mt], bh[nt]);
                }
        }
        __syncthreads();
    }

    // epilogue: fragment layout c0:(gid, qid*2) c1:(gid, qid*2+1) c2:(gid+8, ...) c3
#pragma unroll
    for (int mt = 0; mt < 4; mt++) {
        int r0 = mb * 128 + warpM * 64 + mt * 16 + gid;
#pragma unroll
        for (int nt = 0; nt < 4; nt++) {
            int cn = nb * 128 + warpN * 32 + nt * 8 + qid * 2;
            float b0 = bias ? bias[cn] : 0.f;
            float b1 = bias ? bias[cn + 1] : 0.f;
            if (r0 < M) {
                float v0 = acc[mt][nt][0] + b0;
                float v1 = acc[mt][nt][1] + b1;
                if (doRelu) { v0 = fmaxf(v0, 0.f); v1 = fmaxf(v1, 0.f); }
                C[(size_t)r0 * N + cn] = v0;
                C[(size_t)r0 * N + cn + 1] = v1;
            }
            if (r0 + 8 < M) {
                float v2 = acc[mt][nt][2] + b0;
                float v3 = acc[mt][nt][3] + b1;
                if (doRelu) { v2 = fmaxf(v2, 0.f); v3 = fmaxf(v3, 0.f); }
                C[(size_t)(r0 + 8) * N + cn] = v2;
                C[(size_t)(r0 + 8) * N + cn + 1] = v3;
            }
        }
    }
}

// ---------------- bf16 hi/lo split conversions ----------------
__global__ void k_cvtA(const float* __restrict__ in, __nv_bfloat16* __restrict__ hi,
                       __nv_bfloat16* __restrict__ lo, int n) {
    int i = blockIdx.x * 256 + threadIdx.x;
    if (i < n) {
        float v = in[i];
        __nv_bfloat16 h = __float2bfloat16(v);
        hi[i] = h;
        lo[i] = __float2bfloat16(v - __bfloat162float(h));
    }
}
// weights [K,N] fp32 -> [N,K] bf16 hi/lo (transpose so GEMM B operand is K-contiguous)
__global__ void k_cvtBT(const float* __restrict__ in, __nv_bfloat16* __restrict__ hi,
                        __nv_bfloat16* __restrict__ lo, int K, int N) {
    int i = blockIdx.x * 256 + threadIdx.x;
    if (i < K * N) {
        int kk = i / N, n = i % N;
        float v = in[i];
        __nv_bfloat16 h = __float2bfloat16(v);
        size_t o = (size_t)n * K + kk;
        hi[o] = h;
        lo[o] = __float2bfloat16(v - __bfloat162float(h));
    }
}

// ---------------- small preprocessing kernels ----------------
__global__ void k_zero() {
    int i = blockIdx.x * 256 + threadIdx.x;
    if (i < NN) { g_counts[i] = 0; g_cursor[i] = 0; }
}

__global__ void k_count(const int* __restrict__ dst) {
    int e = blockIdx.x * 256 + threadIdx.x;
    if (e < EE) atomicAdd(&g_counts[dst[e]], 1);
}

__global__ void k_scan() {
    __shared__ int sh[1024];
    int tid = threadIdx.x;
    int carry = 0;
    for (int base = 0; base < NN; base += 1024) {
        int i = base + tid;
        int v = (i < NN) ? g_counts[i] : 0;
        sh[tid] = v;
        __syncthreads();
        for (int off = 1; off < 1024; off <<= 1) {
            int t = (tid >= off) ? sh[tid - off] : 0;
            __syncthreads();
            sh[tid] += t;
            __syncthreads();
        }
        if (i < NN) g_rowptr[i + 1] = carry + sh[tid];
        carry += sh[1023];
        __syncthreads();
    }
    if (tid == 0) g_rowptr[0] = 0;
}

__global__ void k_scatter(const int* __restrict__ src, const int* __restrict__ dst) {
    int e = blockIdx.x * 256 + threadIdx.x;
    if (e < EE) {
        int d = dst[e];
        int pos = g_rowptr[d] + atomicAdd(&g_cursor[d], 1);
        g_csrc[pos] = src[e];
        g_ceid[pos] = e;
    }
}

__global__ void k_wmean(const float* __restrict__ W) {
    __shared__ float red[256];
    int ld = blockIdx.x;
    red[threadIdx.x] = W[(size_t)ld * 256 + threadIdx.x];
    __syncthreads();
    for (int s = 128; s; s >>= 1) {
        if (threadIdx.x < s) red[threadIdx.x] += red[threadIdx.x + s];
        __syncthreads();
    }
    if (threadIdx.x == 0) g_wmean[ld] = red[0] * (1.f / 256.f);
}

__global__ void k_bmean(const float* __restrict__ b) {
    __shared__ float red[256];
    int l = blockIdx.x;
    red[threadIdx.x] = b[l * 256 + threadIdx.x];
    __syncthreads();
    for (int s = 128; s; s >>= 1) {
        if (threadIdx.x < s) red[threadIdx.x] += red[threadIdx.x + s];
        __syncthreads();
    }
    if (threadIdx.x == 0) g_bmean[l] = red[0] * (1.f / 256.f);
}

__global__ void k_cvec(const float* __restrict__ lew, const float* __restrict__ ae) {
    __shared__ float red[256];
    int lh = blockIdx.x;
    size_t off = (size_t)lh * 256 + threadIdx.x;
    red[threadIdx.x] = lew[off] * ae[off];
    __syncthreads();
    for (int s = 128; s; s >>= 1) {
        if (threadIdx.x < s) red[threadIdx.x] += red[threadIdx.x + s];
        __syncthreads();
    }
    if (threadIdx.x == 0) g_cvec[lh] = red[0];
}

__global__ void k_ew(const float* __restrict__ ea, int l) {
    int warp = threadIdx.x >> 5, lane = threadIdx.x & 31;
    int e = blockIdx.x * 8 + warp;
    if (e >= EE) return;
    const float* row = ea + (size_t)e * EDIM;
    const float* wm = g_wmean + l * EDIM;
    float s = 0.f;
    for (int i = lane; i < EDIM; i += 32) s += row[i] * wm[i];
    for (int o = 16; o; o >>= 1) s += __shfl_down_sync(0xffffffff, s, o);
    if (lane == 0) g_ew[e] = s + g_bmean[l];
}

__global__ void k_loopw() {
    int n = blockIdx.x * 256 + threadIdx.x;
    if (n < NN) {
        int b = g_rowptr[n], e = g_rowptr[n + 1];
        float s = 0.f;
        for (int p = b; p < e; p++) s += g_ew[g_ceid[p]];
        float dg = (float)(e - b);
        g_loopw[n] = s / fmaxf(dg, 1.f);
    }
}

// ---------------- attention scores ----------------
__global__ void k_attn(const float* __restrict__ att_s, const float* __restrict__ att_d) {
    int n = blockIdx.x;
    int warp = threadIdx.x >> 5, lane = threadIdx.x & 31;
    const float* xr = g_xp + (size_t)n * 1024 + warp * 256;
    const float* as = att_s + warp * 256;
    const float* ad = att_d + warp * 256;
    float s = 0.f, d = 0.f;
    for (int i = lane; i < 256; i += 32) {
        float v = xr[i];
        s += v * as[i];
        d += v * ad[i];
    }
    for (int o = 16; o; o >>= 1) {
        s += __shfl_down_sync(0xffffffff, s, o);
        d += __shfl_down_sync(0xffffffff, d, o);
    }
    if (lane == 0) {
        g_as[n * 4 + warp] = s;
        g_ad[n * 4 + warp] = d;
    }
}

// ---------------- fused GAT layer ----------------
__device__ __forceinline__ float lrelu(float x) { return fmaxf(x, 0.2f * x); }

#define CH 64
__global__ __launch_bounds__(256) void k_gat(const float* __restrict__ x,
                                             float* __restrict__ xo,
                                             int l,
                                             const float* __restrict__ gat_b,
                                             const float* __restrict__ ln_g,
                                             const float* __restrict__ ln_b) {
    int n = blockIdx.x, tid = threadIdx.x;
    __shared__ float4 red[256];
    __shared__ float wt[CH][4];
    __shared__ int ssrc[CH];
    __shared__ float4 sM, sInv;
    __shared__ float sMu, sVar;

    int beg = g_rowptr[n];
    int deg = g_rowptr[n + 1] - beg;
    int total = deg + 1;

    float c0 = g_cvec[l * 4 + 0], c1 = g_cvec[l * 4 + 1];
    float c2 = g_cvec[l * 4 + 2], c3 = g_cvec[l * 4 + 3];
    float ad0 = g_ad[n * 4 + 0], ad1 = g_ad[n * 4 + 1];
    float ad2 = g_ad[n * 4 + 2], ad3 = g_ad[n * 4 + 3];
    float lw = g_loopw[n];

    float4 lm = make_float4(-1e30f, -1e30f, -1e30f, -1e30f);
    for (int i = tid; i < total; i += 256) {
        int s; float w;
        if (i < deg) { int p = beg + i; s = g_csrc[p]; w = g_ew[g_ceid[p]]; }
        else { s = n; w = lw; }
        float l0 = lrelu(g_as[s * 4 + 0] + ad0 + w * c0);
        float l1 = lrelu(g_as[s * 4 + 1] + ad1 + w * c1);
        float l2 = lrelu(g_as[s * 4 + 2] + ad2 + w * c2);
        float l3 = lrelu(g_as[s * 4 + 3] + ad3 + w * c3);
        lm.x = fmaxf(lm.x, l0); lm.y = fmaxf(lm.y, l1);
        lm.z = fmaxf(lm.z, l2); lm.w = fmaxf(lm.w, l3);
    }
    red[tid] = lm;
    __syncthreads();
    for (int s = 128; s; s >>= 1) {
        if (tid < s) {
            float4 a = red[tid], b = red[tid + s];
            a.x = fmaxf(a.x, b.x); a.y = fmaxf(a.y, b.y);
            a.z = fmaxf(a.z, b.z); a.w = fmaxf(a.w, b.w);
            red[tid] = a;
        }
        __syncthreads();
    }
    if (tid == 0) sM = red[0];
    __syncthreads();
    float4 m = sM;
    __syncthreads();

    float4 ls = make_float4(0.f, 0.f, 0.f, 0.f);
    for (int i = tid; i < total; i += 256) {
        int s; float w;
        if (i < deg) { int p = beg + i; s = g_csrc[p]; w = g_ew[g_ceid[p]]; }
        else { s = n; w = lw; }
        ls.x += expf(lrelu(g_as[s * 4 + 0] + ad0 + w * c0) - m.x);
        ls.y += expf(lrelu(g_as[s * 4 + 1] + ad1 + w * c1) - m.y);
        ls.z += expf(lrelu(g_as[s * 4 + 2] + ad2 + w * c2) - m.z);
        ls.w += expf(lrelu(g_as[s * 4 + 3] + ad3 + w * c3) - m.w);
    }
    red[tid] = ls;
    __syncthreads();
    for (int s = 128; s; s >>= 1) {
        if (tid < s) {
            float4 a = red[tid], b = red[tid + s];
            a.x += b.x; a.y += b.y; a.z += b.z; a.w += b.w;
            red[tid] = a;
        }
        __syncthreads();
    }
    if (tid == 0) {
        float4 t = red[0];
        sInv = make_float4(0.25f / t.x, 0.25f / t.y, 0.25f / t.z, 0.25f / t.w);
    }
    __syncthreads();
    float4 inv = sInv;

    float acc = 0.f;
    for (int ch = 0; ch < total; ch += CH) {
        int cnt = min(CH, total - ch);
        __syncthreads();
        if (tid < cnt) {
            int i = ch + tid;
            int s; float w;
            if (i < deg) { int p = beg + i; s = g_csrc[p]; w = g_ew[g_ceid[p]]; }
            else { s = n; w = lw; }
            wt[tid][0] = expf(lrelu(g_as[s * 4 + 0] + ad0 + w * c0) - m.x) * inv.x;
            wt[tid][1] = expf(lrelu(g_as[s * 4 + 1] + ad1 + w * c1) - m.y) * inv.y;
            wt[tid][2] = expf(lrelu(g_as[s * 4 + 2] + ad2 + w * c2) - m.z) * inv.z;
            wt[tid][3] = expf(lrelu(g_as[s * 4 + 3] + ad3 + w * c3) - m.w) * inv.w;
            ssrc[tid] = s;
        }
        __syncthreads();
        for (int j = 0; j < cnt; j++) {
            const float* xr = g_xp + (size_t)ssrc[j] * 1024;
            acc += wt[j][0] * xr[tid] + wt[j][1] * xr[256 + tid] +
                   wt[j][2] * xr[512 + tid] + wt[j][3] * xr[768 + tid];
        }
    }

    float h = acc + gat_b[tid];

    float* redf = (float*)red;
    __syncthreads();
    redf[tid] = h;
    __syncthreads();
    for (int s = 128; s; s >>= 1) {
        if (tid < s) redf[tid] += redf[tid + s];
        __syncthreads();
    }
    if (tid == 0) sMu = redf[0] * (1.f / 256.f);
    __syncthreads();
    float mu = sMu;
    float df = h - mu;
    __syncthreads();
    redf[tid] = df * df;
    __syncthreads();
    for (int s = 128; s; s >>= 1) {
        if (tid < s) redf[tid] += redf[tid + s];
        __syncthreads();
    }
    if (tid == 0) sVar = redf[0] * (1.f / 256.f);
    __syncthreads();
    float var = sVar;

    float y = ln_g[tid] * df * rsqrtf(var + 1e-5f) + ln_b[tid];
    size_t idx = (size_t)n * 256 + tid;
    xo[idx] = fmaxf(x[idx] + y, 0.f);
}

// ---------------- prediction heads epilogue ----------------
__global__ void k_headout(const float* __restrict__ w2, const float* __restrict__ b2,
                          float* __restrict__ out) {
    int n = blockIdx.x;
    int k = threadIdx.x >> 5, lane = threadIdx.x & 31;
    const float* hr = g_hmid + ((size_t)k * NN + n) * 128;
    const float* w = w2 + k * 128;
    float s = 0.f;
    for (int i = lane; i < 128; i += 32) s += hr[i] * w[i];
    for (int o = 16; o; o >>= 1) s += __shfl_down_sync(0xffffffff, s, o);
    if (lane == 0) {
        float v = s + b2[k];
        if (k == 0 || k == 3) v = 1.f / (1.f + expf(-v));
        out[(size_t)k * NN + n] = v;
    }
}

__global__ void k_emb(const float* __restrict__ emb, float* __restrict__ out) {
    size_t i = (size_t)blockIdx.x * 256 + threadIdx.x;
    if (i < (size_t)NN * HD) out[(size_t)4 * NN + i] = emb[i];
}

// ---------------- launch ----------------
extern "C" void kernel_launch(void* const* d_in, const int* in_sizes, int n_in,
                              void* d_out, int out_size) {
    const float* node_features = (const float*)d_in[0];
    const float* edge_attr     = (const float*)d_in[1];
    const float* enc_w         = (const float*)d_in[2];
    const float* enc_b         = (const float*)d_in[3];
    const float* edge_enc_w    = (const float*)d_in[4];
    const float* edge_enc_b    = (const float*)d_in[5];
    const float* gat_w         = (const float*)d_in[6];
    const float* att_src       = (const float*)d_in[7];
    const float* att_dst       = (const float*)d_in[8];
    const float* att_edge      = (const float*)d_in[9];
    const float* lin_edge_w    = (const float*)d_in[10];
    const float* gat_b         = (const float*)d_in[11];
    const float* ln_g          = (const float*)d_in[12];
    const float* ln_b          = (const float*)d_in[13];
    const float* head_w1       = (const float*)d_in[14];
    const float* head_b1       = (const float*)d_in[15];
    const float* head_w2       = (const float*)d_in[16];
    const float* head_b2       = (const float*)d_in[17];
    const int*   src           = (const int*)d_in[18];
    const int*   dst           = src + EE;
    float* out = (float*)d_out;

    float *px, *px2, *pxp, *phmid;
    __nv_bfloat16 *pAh, *pAl, *pBh, *pBl;
    cudaGetSymbolAddress((void**)&px, g_x);
    cudaGetSymbolAddress((void**)&px2, g_x2);
    cudaGetSymbolAddress((void**)&pxp, g_xp);
    cudaGetSymbolAddress((void**)&phmid, g_hmid);
    cudaGetSymbolAddress((void**)&pAh, g_Ah);
    cudaGetSymbolAddress((void**)&pAl, g_Al);
    cudaGetSymbolAddress((void**)&pBh, g_Bh);
    cudaGetSymbolAddress((void**)&pBl, g_Bl);

    cudaFuncSetAttribute(k_mma, cudaFuncAttributeMaxDynamicSharedMemorySize, GEMM_SMEM);

    const int MT = (NN + 127) / 128;  // 157 M-tiles

    // ---- graph preprocessing (dst-CSR) + per-layer constants ----
    k_zero<<<(NN + 255) / 256, 256>>>();
    k_count<<<(EE + 255) / 256, 256>>>(dst);
    k_scan<<<1, 1024>>>();
    k_scatter<<<(EE + 255) / 256, 256>>>(src, dst);
    k_wmean<<<NL * EDIM, 256>>>(edge_enc_w);
    k_bmean<<<NL, 256>>>(edge_enc_b);
    k_cvec<<<NL * NHEADS, 256>>>(lin_edge_w, att_edge);

    // ---- encoder: x = relu(nf @ enc_w + enc_b)   [20000,128]@[128,256] ----
    k_cvtA<<<(NN * NDIM + 255) / 256, 256>>>(node_features, pAh, pAl, NN * NDIM);
    k_cvtBT<<<(NDIM * HD + 255) / 256, 256>>>(enc_w, pBh, pBl, NDIM, HD);
    k_mma<<<dim3(HD / 128, MT), 256, GEMM_SMEM>>>(pAh, pAl, pBh, pBl, px,
                                                  NN, HD, NDIM, enc_b, 1);

    // ---- 3 GAT layers ----
    for (int l = 0; l < NL; l++) {
        const float* A = (l & 1) ? px2 : px;
        float* XO      = (l & 1) ? px  : px2;

        // xp = x @ gat_w[l]   [20000,256]@[256,1024]
        k_cvtA<<<(NN * HD + 255) / 256, 256>>>(A, pAh, pAl, NN * HD);
        k_cvtBT<<<(HD * 1024 + 255) / 256, 256>>>(gat_w + (size_t)l * 256 * 1024,
                                                  pBh, pBl, HD, 1024);
        k_mma<<<dim3(1024 / 128, MT), 256, GEMM_SMEM>>>(pAh, pAl, pBh, pBl, pxp,
                                                        NN, 1024, HD, nullptr, 0);

        k_attn<<<NN, 128>>>(att_src + l * 1024, att_dst + l * 1024);
        k_ew<<<(EE + 7) / 8, 256>>>(edge_attr, l);
        k_loopw<<<(NN + 255) / 256, 256>>>();
        k_gat<<<NN, 256>>>(A, XO, l, gat_b + l * 256, ln_g + l * 256, ln_b + l * 256);
    }
    // after l=2, emb lives in px2

    // ---- 4 prediction heads: hmid = relu(emb @ W1 + b1)   [20000,256]@[256,128] ----
    k_cvtA<<<(NN * HD + 255) / 256, 256>>>(px2, pAh, pAl, NN * HD);
    for (int k = 0; k < 4; k++) {
        k_cvtBT<<<(HD * 128 + 255) / 256, 256>>>(head_w1 + (size_t)k * 256 * 128,
                                                 pBh, pBl, HD, 128);
        k_mma<<<dim3(128 / 128, MT), 256, GEMM_SMEM>>>(pAh, pAl, pBh, pBl,
                                                       phmid + (size_t)k * NN * 128,
                                                       NN, 128, HD, head_b1 + k * 128, 1);
    }
    k_headout<<<NN, 128>>>(head_w2, head_b2, out);
    if (out_size >= 4 * NN + NN * HD)
        k_emb<<<((size_t)NN * HD + 255) / 256, 256>>>(px2, out);
}

// round 5
// speedup vs baseline: 1.8445x; 1.2608x over previous
#include <cuda_runtime.h>
#include <cuda_bf16.h>
#include <cstdint>
#include <math.h>

#define NN 20000
#define EE 200000
#define HD 256
#define NHEADS 4
#define NDIM 128
#define EDIM 64
#define NL 3

// ---------------- scratch (static device globals; no runtime allocation) ----------------
__device__ float g_x  [(size_t)NN * HD];
__device__ float g_x2 [(size_t)NN * HD];
__device__ float g_xp [(size_t)NN * NHEADS * HD];   // [N, 4, 256] = [N,1024]
__device__ float g_as [NN * NHEADS];
__device__ float g_ad [NN * NHEADS];
__device__ float g_ew [NL * EE];
__device__ float g_loopw[NL * NN];
__device__ int   g_counts[NN];
__device__ int   g_cursor[NN];
__device__ int   g_rowptr[NN + 1];
__device__ int   g_csrc[EE];
__device__ int   g_ceid[EE];
__device__ float g_hmid[4 * (size_t)NN * (HD / 2)];
__device__ float g_wmean[NL * EDIM];
__device__ float g_bmean[NL];
__device__ float g_cvec [NL * NHEADS];
// edge-parallel softmax state
__device__ unsigned g_maxu[NN * NHEADS];
__device__ float g_sum  [NN * NHEADS];
__device__ float g_selfl[NN * NHEADS];
__device__ float g_selfp[NN * NHEADS];
__device__ float g_palpha[(size_t)EE * NHEADS];
// bf16 split buffers for tensor-core GEMM
__device__ __nv_bfloat16 g_Ah[(size_t)NN * HD];
__device__ __nv_bfloat16 g_Al[(size_t)NN * HD];
__device__ __nv_bfloat16 g_Bh[1024 * 256];
__device__ __nv_bfloat16 g_Bl[1024 * 256];

// ---------------- helpers ----------------
__device__ __forceinline__ uint32_t fkey(float f) {
    uint32_t u = __float_as_uint(f);
    return (u & 0x80000000u) ? ~u : (u | 0x80000000u);
}
__device__ __forceinline__ float funkey(uint32_t k) {
    uint32_t u = (k & 0x80000000u) ? (k ^ 0x80000000u) : ~k;
    return __uint_as_float(u);
}
__device__ __forceinline__ float lrelu(float x) { return fmaxf(x, 0.2f * x); }

__device__ __forceinline__ void mma16816(float* c, const uint32_t* a, const uint32_t* b) {
    asm volatile(
        "mma.sync.aligned.m16n8k16.row.col.f32.bf16.bf16.f32 "
        "{%0,%1,%2,%3}, {%4,%5,%6,%7}, {%8,%9}, {%0,%1,%2,%3};"
        : "+f"(c[0]), "+f"(c[1]), "+f"(c[2]), "+f"(c[3])
        : "r"(a[0]), "r"(a[1]), "r"(a[2]), "r"(a[3]), "r"(b[0]), "r"(b[1]));
}
__device__ __forceinline__ void ldsm4(uint32_t addr, uint32_t* r) {
    asm volatile("ldmatrix.sync.aligned.m8n8.x4.shared.b16 {%0,%1,%2,%3}, [%4];"
                 : "=r"(r[0]), "=r"(r[1]), "=r"(r[2]), "=r"(r[3]) : "r"(addr));
}
__device__ __forceinline__ void cpa16(uint32_t dst, const void* src) {
    asm volatile("cp.async.cg.shared.global [%0], [%1], 16;" :: "r"(dst), "l"(src));
}
__device__ __forceinline__ void cpa_commit_wait() {
    asm volatile("cp.async.commit_group;");
    asm volatile("cp.async.wait_group 0;" ::: "memory");
}

// ---------------- bf16x3 GEMM: C[M,N] = A[M,K]@B[K,N] (+bias)(+relu) ----------------
// A as bf16 hi/lo [M,K] row-major; B pre-transposed+split as [N,K] row-major (K-contiguous).
// Block tile 128x128, 8 warps (2Mx4N), warp tile 64x32, K-chunk 64. cp.async + ldmatrix.
#define KCH 64
#define AST 72                         // smem row stride in bf16 (144B = 9*16B, conflict-free)
#define GEMM_SMEM (4 * 128 * AST * 2)  // 73728 bytes
__global__ __launch_bounds__(256) void k_mma(
    const __nv_bfloat16* __restrict__ Ah, const __nv_bfloat16* __restrict__ Al,
    const __nv_bfloat16* __restrict__ Bh, const __nv_bfloat16* __restrict__ Bl,
    float* __restrict__ C, int M, int N, int K,
    const float* __restrict__ bias, int doRelu) {
    extern __shared__ __nv_bfloat16 sm[];
    __nv_bfloat16* sAh = sm;
    __nv_bfloat16* sAl = sm + 128 * AST;
    __nv_bfloat16* sBh = sm + 2 * 128 * AST;
    __nv_bfloat16* sBl = sm + 3 * 128 * AST;
    uint32_t uAh = (uint32_t)__cvta_generic_to_shared(sAh);
    uint32_t uAl = (uint32_t)__cvta_generic_to_shared(sAl);
    uint32_t uBh = (uint32_t)__cvta_generic_to_shared(sBh);
    uint32_t uBl = (uint32_t)__cvta_generic_to_shared(sBl);

    int tid = threadIdx.x, lane = tid & 31, wid = tid >> 5;
    int nb = blockIdx.x, mb = blockIdx.y;
    int warpM = wid >> 2, warpN = wid & 3;
    int gid = lane >> 2, qid = lane & 3;

    float acc[4][4][4];
#pragma unroll
    for (int i = 0; i < 4; i++)
#pragma unroll
        for (int j = 0; j < 4; j++)
#pragma unroll
            for (int k = 0; k < 4; k++) acc[i][j][k] = 0.f;

    // ldmatrix lane addressing (bf16-element offsets within tile)
    int aRow = (lane & 15), aCol = (lane >> 4) * 8;                    // A x4: rows0-15, +-8k
    int bRow = (lane & 7) + ((lane >> 4) << 3), bCol = ((lane >> 3) & 1) * 8;  // B x4 (2 nt)

    for (int kc = 0; kc < K; kc += KCH) {
        // A chunk: 128 rows x 64 bf16 (hi+lo) via cp.async
#pragma unroll
        for (int i = tid; i < 1024; i += 256) {
            int row = i >> 3, c = i & 7;
            int gr = mb * 128 + row;
            uint32_t so = (uint32_t)(row * AST + c * 8) * 2;
            if (gr < M) {
                cpa16(uAh + so, Ah + (size_t)gr * K + kc + c * 8);
                cpa16(uAl + so, Al + (size_t)gr * K + kc + c * 8);
            } else {
                *(int4*)(sAh + row * AST + c * 8) = make_int4(0, 0, 0, 0);
                *(int4*)(sAl + row * AST + c * 8) = make_int4(0, 0, 0, 0);
            }
        }
        // B chunk: 128 n-rows x 64 bf16 (hi+lo); N always multiple of 128
#pragma unroll
        for (int i = tid; i < 1024; i += 256) {
            int row = i >> 3, c = i & 7;
            int gn = nb * 128 + row;
            uint32_t so = (uint32_t)(row * AST + c * 8) * 2;
            cpa16(uBh + so, Bh + (size_t)gn * K + kc + c * 8);
            cpa16(uBl + so, Bl + (size_t)gn * K + kc + c * 8);
        }
        cpa_commit_wait();
        __syncthreads();

#pragma unroll
        for (int ks = 0; ks < KCH; ks += 16) {
            uint32_t ah[4][4], al[4][4], bh[2][4], bl[2][4];
#pragma unroll
            for (int mt = 0; mt < 4; mt++) {
                uint32_t off = (uint32_t)((warpM * 64 + mt * 16 + aRow) * AST + ks + aCol) * 2;
                ldsm4(uAh + off, ah[mt]);
                ldsm4(uAl + off, al[mt]);
            }
#pragma unroll
            for (int np = 0; np < 2; np++) {
                uint32_t off = (uint32_t)((warpN * 32 + np * 16 + bRow) * AST + ks + bCol) * 2;
                ldsm4(uBh + off, bh[np]);
                ldsm4(uBl + off, bl[np]);
            }
#pragma unroll
            for (int mt = 0; mt < 4; mt++)
#pragma unroll
                for (int nt = 0; nt < 4; nt++) {
                    const uint32_t* bhp = &bh[nt >> 1][(nt & 1) * 2];
                    const uint32_t* blp = &bl[nt >> 1][(nt & 1) * 2];
                    mma16816(acc[mt][nt], ah[mt], bhp);
                    mma16816(acc[mt][nt], ah[mt], blp);
                    mma16816(acc[mt][nt], al[mt], bhp);
                }
        }
        __syncthreads();
    }

    // epilogue: c0:(gid, qid*2) c1:(gid, qid*2+1) c2:(gid+8, qid*2) c3:(gid+8, qid*2+1)
#pragma unroll
    for (int mt = 0; mt < 4; mt++) {
        int r0 = mb * 128 + warpM * 64 + mt * 16 + gid;
#pragma unroll
        for (int nt = 0; nt < 4; nt++) {
            int cn = nb * 128 + warpN * 32 + nt * 8 + qid * 2;
            float b0 = bias ? bias[cn] : 0.f;
            float b1 = bias ? bias[cn + 1] : 0.f;
            if (r0 < M) {
                float v0 = acc[mt][nt][0] + b0;
                float v1 = acc[mt][nt][1] + b1;
                if (doRelu) { v0 = fmaxf(v0, 0.f); v1 = fmaxf(v1, 0.f); }
                C[(size_t)r0 * N + cn] = v0;
                C[(size_t)r0 * N + cn + 1] = v1;
            }
            if (r0 + 8 < M) {
                float v2 = acc[mt][nt][2] + b0;
                float v3 = acc[mt][nt][3] + b1;
                if (doRelu) { v2 = fmaxf(v2, 0.f); v3 = fmaxf(v3, 0.f); }
                C[(size_t)(r0 + 8) * N + cn] = v2;
                C[(size_t)(r0 + 8) * N + cn + 1] = v3;
            }
        }
    }
}

// ---------------- bf16 hi/lo split conversions ----------------
__global__ void k_cvtA(const float* __restrict__ in, __nv_bfloat16* __restrict__ hi,
                       __nv_bfloat16* __restrict__ lo, int n) {
    int i = blockIdx.x * 256 + threadIdx.x;
    if (i < n) {
        float v = in[i];
        __nv_bfloat16 h = __float2bfloat16(v);
        hi[i] = h;
        lo[i] = __float2bfloat16(v - __bfloat162float(h));
    }
}
__global__ void k_cvtBT(const float* __restrict__ in, __nv_bfloat16* __restrict__ hi,
                        __nv_bfloat16* __restrict__ lo, int K, int N) {
    int i = blockIdx.x * 256 + threadIdx.x;
    if (i < K * N) {
        int kk = i / N, n = i % N;
        float v = in[i];
        __nv_bfloat16 h = __float2bfloat16(v);
        size_t o = (size_t)n * K + kk;
        hi[o] = h;
        lo[o] = __float2bfloat16(v - __bfloat162float(h));
    }
}

// ---------------- preprocessing ----------------
__global__ void k_zero() {
    int i = blockIdx.x * 256 + threadIdx.x;
    if (i < NN) { g_counts[i] = 0; g_cursor[i] = 0; }
}
__global__ void k_count(const int* __restrict__ dst) {
    int e = blockIdx.x * 256 + threadIdx.x;
    if (e < EE) atomicAdd(&g_counts[dst[e]], 1);
}
__global__ void k_scan() {
    __shared__ int sh[1024];
    int tid = threadIdx.x;
    int carry = 0;
    for (int base = 0; base < NN; base += 1024) {
        int i = base + tid;
        int v = (i < NN) ? g_counts[i] : 0;
        sh[tid] = v;
        __syncthreads();
        for (int off = 1; off < 1024; off <<= 1) {
            int t = (tid >= off) ? sh[tid - off] : 0;
            __syncthreads();
            sh[tid] += t;
            __syncthreads();
        }
        if (i < NN) g_rowptr[i + 1] = carry + sh[tid];
        carry += sh[1023];
        __syncthreads();
    }
    if (tid == 0) g_rowptr[0] = 0;
}
__global__ void k_scatter(const int* __restrict__ src, const int* __restrict__ dst) {
    int e = blockIdx.x * 256 + threadIdx.x;
    if (e < EE) {
        int d = dst[e];
        int pos = g_rowptr[d] + atomicAdd(&g_cursor[d], 1);
        g_csrc[pos] = src[e];
        g_ceid[pos] = e;
    }
}
__global__ void k_wmean(const float* __restrict__ W) {
    __shared__ float red[256];
    int ld = blockIdx.x;
    red[threadIdx.x] = W[(size_t)ld * 256 + threadIdx.x];
    __syncthreads();
    for (int s = 128; s; s >>= 1) {
        if (threadIdx.x < s) red[threadIdx.x] += red[threadIdx.x + s];
        __syncthreads();
    }
    if (threadIdx.x == 0) g_wmean[ld] = red[0] * (1.f / 256.f);
}
__global__ void k_bmean(const float* __restrict__ b) {
    __shared__ float red[256];
    int l = blockIdx.x;
    red[threadIdx.x] = b[l * 256 + threadIdx.x];
    __syncthreads();
    for (int s = 128; s; s >>= 1) {
        if (threadIdx.x < s) red[threadIdx.x] += red[threadIdx.x + s];
        __syncthreads();
    }
    if (threadIdx.x == 0) g_bmean[l] = red[0] * (1.f / 256.f);
}
__global__ void k_cvec(const float* __restrict__ lew, const float* __restrict__ ae) {
    __shared__ float red[256];
    int lh = blockIdx.x;
    size_t off = (size_t)lh * 256 + threadIdx.x;
    red[threadIdx.x] = lew[off] * ae[off];
    __syncthreads();
    for (int s = 128; s; s >>= 1) {
        if (threadIdx.x < s) red[threadIdx.x] += red[threadIdx.x + s];
        __syncthreads();
    }
    if (threadIdx.x == 0) g_cvec[lh] = red[0];
}

// ew for ALL layers in one pass over edge_attr (warp per edge)
__global__ void k_ew3(const float* __restrict__ ea) {
    int warp = threadIdx.x >> 5, lane = threadIdx.x & 31;
    int e = blockIdx.x * 8 + warp;
    if (e >= EE) return;
    const float* row = ea + (size_t)e * EDIM;
    float v0 = row[lane], v1 = row[lane + 32];
    float s0 = v0 * g_wmean[lane] + v1 * g_wmean[lane + 32];
    float s1 = v0 * g_wmean[64 + lane] + v1 * g_wmean[64 + lane + 32];
    float s2 = v0 * g_wmean[128 + lane] + v1 * g_wmean[128 + lane + 32];
    for (int o = 16; o; o >>= 1) {
        s0 += __shfl_down_sync(0xffffffff, s0, o);
        s1 += __shfl_down_sync(0xffffffff, s1, o);
        s2 += __shfl_down_sync(0xffffffff, s2, o);
    }
    if (lane == 0) {
        g_ew[e] = s0 + g_bmean[0];
        g_ew[EE + e] = s1 + g_bmean[1];
        g_ew[2 * EE + e] = s2 + g_bmean[2];
    }
}

__global__ void k_loopw3() {
    int n = blockIdx.x * 256 + threadIdx.x;
    if (n < NN) {
        int b = g_rowptr[n], e = g_rowptr[n + 1];
        float s0 = 0.f, s1 = 0.f, s2 = 0.f;
        for (int p = b; p < e; p++) {
            int id = g_ceid[p];
            s0 += g_ew[id];
            s1 += g_ew[EE + id];
            s2 += g_ew[2 * EE + id];
        }
        float inv = 1.f / fmaxf((float)(e - b), 1.f);
        g_loopw[n] = s0 * inv;
        g_loopw[NN + n] = s1 * inv;
        g_loopw[2 * NN + n] = s2 * inv;
    }
}

// ---------------- attention scores + self-loop logit init (warp per head) ----------------
__global__ void k_attn2(const float* __restrict__ att_s, const float* __restrict__ att_d, int l) {
    int n = blockIdx.x;
    int warp = threadIdx.x >> 5, lane = threadIdx.x & 31;
    const float* xr = g_xp + (size_t)n * 1024 + warp * 256;
    const float* as = att_s + warp * 256;
    const float* ad = att_d + warp * 256;
    float s = 0.f, d = 0.f;
    for (int i = lane; i < 256; i += 32) {
        float v = xr[i];
        s += v * as[i];
        d += v * ad[i];
    }
    for (int o = 16; o; o >>= 1) {
        s += __shfl_down_sync(0xffffffff, s, o);
        d += __shfl_down_sync(0xffffffff, d, o);
    }
    if (lane == 0) {
        g_as[n * 4 + warp] = s;
        g_ad[n * 4 + warp] = d;
        float self = lrelu(s + d + g_loopw[l * NN + n] * g_cvec[l * 4 + warp]);
        g_selfl[n * 4 + warp] = self;
        g_maxu[n * 4 + warp] = fkey(self);
    }
}

// edge-parallel: logits + segment max (atomicMax on orderable uint)
__global__ void k_smax(const int* __restrict__ src, const int* __restrict__ dst, int l) {
    int e = blockIdx.x * 256 + threadIdx.x;
    if (e >= EE) return;
    int s = src[e], d = dst[e];
    float w = g_ew[l * EE + e];
    float4 as4 = *(const float4*)&g_as[s * 4];
    float4 ad4 = *(const float4*)&g_ad[d * 4];
    float l0 = lrelu(as4.x + ad4.x + w * g_cvec[l * 4 + 0]);
    float l1 = lrelu(as4.y + ad4.y + w * g_cvec[l * 4 + 1]);
    float l2 = lrelu(as4.z + ad4.z + w * g_cvec[l * 4 + 2]);
    float l3 = lrelu(as4.w + ad4.w + w * g_cvec[l * 4 + 3]);
    *(float4*)&g_palpha[(size_t)e * 4] = make_float4(l0, l1, l2, l3);
    atomicMax(&g_maxu[d * 4 + 0], fkey(l0));
    atomicMax(&g_maxu[d * 4 + 1], fkey(l1));
    atomicMax(&g_maxu[d * 4 + 2], fkey(l2));
    atomicMax(&g_maxu[d * 4 + 3], fkey(l3));
}

// per node-head: self p, init sum
__global__ void k_selfsum() {
    int i = blockIdx.x * 256 + threadIdx.x;
    if (i < NN * 4) {
        float mx = funkey(g_maxu[i]);
        float p = expf(g_selfl[i] - mx);
        g_selfp[i] = p;
        g_sum[i] = p;
    }
}

// edge-parallel: p = exp(logit - max), accumulate segment sums
__global__ void k_sexp(const int* __restrict__ dst) {
    int e = blockIdx.x * 256 + threadIdx.x;
    if (e >= EE) return;
    int d = dst[e];
    float4 lg = *(const float4*)&g_palpha[(size_t)e * 4];
    float p0 = expf(lg.x - funkey(g_maxu[d * 4 + 0]));
    float p1 = expf(lg.y - funkey(g_maxu[d * 4 + 1]));
    float p2 = expf(lg.z - funkey(g_maxu[d * 4 + 2]));
    float p3 = expf(lg.w - funkey(g_maxu[d * 4 + 3]));
    *(float4*)&g_palpha[(size_t)e * 4] = make_float4(p0, p1, p2, p3);
    atomicAdd(&g_sum[d * 4 + 0], p0);
    atomicAdd(&g_sum[d * 4 + 1], p1);
    atomicAdd(&g_sum[d * 4 + 2], p2);
    atomicAdd(&g_sum[d * 4 + 3], p3);
}

// ---------------- gather + bias + LN + residual relu (block per node) ----------------
#define CH 64
__global__ __launch_bounds__(256) void k_gather(const float* __restrict__ x,
                                                float* __restrict__ xo,
                                                const float* __restrict__ gat_b,
                                                const float* __restrict__ ln_g,
                                                const float* __restrict__ ln_b) {
    int n = blockIdx.x, tid = threadIdx.x;
    int lane = tid & 31, wid = tid >> 5;
    int head = tid >> 6, d4 = (tid & 63) * 4;   // thread -> (head, 4 features)
    __shared__ float inv4[4];
    __shared__ int ssrc[CH];
    __shared__ float wt[CH][4];
    __shared__ float sred[1024];
    __shared__ float sw[8];
    __shared__ float sMu, sVar;

    int beg = g_rowptr[n];
    int deg = g_rowptr[n + 1] - beg;

    if (tid < 4) inv4[tid] = 0.25f / g_sum[n * 4 + tid];
    __syncthreads();

    const float4* xp4 = (const float4*)g_xp;
    // self-loop contribution
    float a_self = g_selfp[n * 4 + head] * inv4[head];
    float4 xv = xp4[(size_t)n * 256 + head * 64 + (d4 >> 2)];
    float4 acc = make_float4(a_self * xv.x, a_self * xv.y, a_self * xv.z, a_self * xv.w);

    for (int ch = 0; ch < deg; ch += CH) {
        int cnt = min(CH, deg - ch);
        __syncthreads();
        if (tid < cnt) {
            int p = beg + ch + tid;
            int e = g_ceid[p];
            ssrc[tid] = g_csrc[p];
            float4 pa = *(const float4*)&g_palpha[(size_t)e * 4];
            wt[tid][0] = pa.x * inv4[0];
            wt[tid][1] = pa.y * inv4[1];
            wt[tid][2] = pa.z * inv4[2];
            wt[tid][3] = pa.w * inv4[3];
        }
        __syncthreads();
        for (int j = 0; j < cnt; j++) {
            float a = wt[j][head];
            float4 v = xp4[(size_t)ssrc[j] * 256 + head * 64 + (d4 >> 2)];
            acc.x += a * v.x;
            acc.y += a * v.y;
            acc.z += a * v.z;
            acc.w += a * v.w;
        }
    }
    __syncthreads();
    *(float4*)&sred[head * 256 + d4] = acc;
    __syncthreads();

    // thread tid owns feature d=tid: sum over heads
    float h = sred[tid] + sred[256 + tid] + sred[512 + tid] + sred[768 + tid] + gat_b[tid];

    // layernorm via warp shuffles (8 warps)
    float v = h;
    for (int o = 16; o; o >>= 1) v += __shfl_xor_sync(0xffffffff, v, o);
    if (lane == 0) sw[wid] = v;
    __syncthreads();
    if (tid == 0) {
        float t = sw[0] + sw[1] + sw[2] + sw[3] + sw[4] + sw[5] + sw[6] + sw[7];
        sMu = t * (1.f / 256.f);
    }
    __syncthreads();
    float mu = sMu;
    float df = h - mu;
    v = df * df;
    for (int o = 16; o; o >>= 1) v += __shfl_xor_sync(0xffffffff, v, o);
    __syncthreads();
    if (lane == 0) sw[wid] = v;
    __syncthreads();
    if (tid == 0) {
        float t = sw[0] + sw[1] + sw[2] + sw[3] + sw[4] + sw[5] + sw[6] + sw[7];
        sVar = t * (1.f / 256.f);
    }
    __syncthreads();
    float y = ln_g[tid] * df * rsqrtf(sVar + 1e-5f) + ln_b[tid];
    size_t idx = (size_t)n * 256 + tid;
    xo[idx] = fmaxf(x[idx] + y, 0.f);
}

// ---------------- prediction heads epilogue ----------------
__global__ void k_headout(const float* __restrict__ w2, const float* __restrict__ b2,
                          float* __restrict__ out) {
    int n = blockIdx.x;
    int k = threadIdx.x >> 5, lane = threadIdx.x & 31;
    const float* hr = g_hmid + ((size_t)k * NN + n) * 128;
    const float* w = w2 + k * 128;
    float s = 0.f;
    for (int i = lane; i < 128; i += 32) s += hr[i] * w[i];
    for (int o = 16; o; o >>= 1) s += __shfl_down_sync(0xffffffff, s, o);
    if (lane == 0) {
        float v = s + b2[k];
        if (k == 0 || k == 3) v = 1.f / (1.f + expf(-v));
        out[(size_t)k * NN + n] = v;
    }
}

__global__ void k_emb(const float* __restrict__ emb, float* __restrict__ out) {
    size_t i = (size_t)blockIdx.x * 256 + threadIdx.x;
    if (i < (size_t)NN * HD) out[(size_t)4 * NN + i] = emb[i];
}

// ---------------- launch ----------------
extern "C" void kernel_launch(void* const* d_in, const int* in_sizes, int n_in,
                              void* d_out, int out_size) {
    const float* node_features = (const float*)d_in[0];
    const float* edge_attr     = (const float*)d_in[1];
    const float* enc_w         = (const float*)d_in[2];
    const float* enc_b         = (const float*)d_in[3];
    const float* edge_enc_w    = (const float*)d_in[4];
    const float* edge_enc_b    = (const float*)d_in[5];
    const float* gat_w         = (const float*)d_in[6];
    const float* att_src       = (const float*)d_in[7];
    const float* att_dst       = (const float*)d_in[8];
    const float* att_edge      = (const float*)d_in[9];
    const float* lin_edge_w    = (const float*)d_in[10];
    const float* gat_b         = (const float*)d_in[11];
    const float* ln_g          = (const float*)d_in[12];
    const float* ln_b          = (const float*)d_in[13];
    const float* head_w1       = (const float*)d_in[14];
    const float* head_b1       = (const float*)d_in[15];
    const float* head_w2       = (const float*)d_in[16];
    const float* head_b2       = (const float*)d_in[17];
    const int*   src           = (const int*)d_in[18];
    const int*   dst           = src + EE;
    float* out = (float*)d_out;

    float *px, *px2, *pxp, *phmid;
    __nv_bfloat16 *pAh, *pAl, *pBh, *pBl;
    cudaGetSymbolAddress((void**)&px, g_x);
    cudaGetSymbolAddress((void**)&px2, g_x2);
    cudaGetSymbolAddress((void**)&pxp, g_xp);
    cudaGetSymbolAddress((void**)&phmid, g_hmid);
    cudaGetSymbolAddress((void**)&pAh, g_Ah);
    cudaGetSymbolAddress((void**)&pAl, g_Al);
    cudaGetSymbolAddress((void**)&pBh, g_Bh);
    cudaGetSymbolAddress((void**)&pBl, g_Bl);

    cudaFuncSetAttribute(k_mma, cudaFuncAttributeMaxDynamicSharedMemorySize, GEMM_SMEM);

    const int MT = (NN + 127) / 128;  // 157 M-tiles

    // ---- graph preprocessing (dst-CSR) + per-layer constants ----
    k_zero<<<(NN + 255) / 256, 256>>>();
    k_count<<<(EE + 255) / 256, 256>>>(dst);
    k_scan<<<1, 1024>>>();
    k_scatter<<<(EE + 255) / 256, 256>>>(src, dst);
    k_wmean<<<NL * EDIM, 256>>>(edge_enc_w);
    k_bmean<<<NL, 256>>>(edge_enc_b);
    k_cvec<<<NL * NHEADS, 256>>>(lin_edge_w, att_edge);
    k_ew3<<<(EE + 7) / 8, 256>>>(edge_attr);
    k_loopw3<<<(NN + 255) / 256, 256>>>();

    // ---- encoder: x = relu(nf @ enc_w + enc_b)   [20000,128]@[128,256] ----
    k_cvtA<<<(NN * NDIM + 255) / 256, 256>>>(node_features, pAh, pAl, NN * NDIM);
    k_cvtBT<<<(NDIM * HD + 255) / 256, 256>>>(enc_w, pBh, pBl, NDIM, HD);
    k_mma<<<dim3(HD / 128, MT), 256, GEMM_SMEM>>>(pAh, pAl, pBh, pBl, px,
                                                  NN, HD, NDIM, enc_b, 1);

    // ---- 3 GAT layers ----
    for (int l = 0; l < NL; l++) {
        const float* A = (l & 1) ? px2 : px;
        float* XO      = (l & 1) ? px  : px2;

        // xp = x @ gat_w[l]   [20000,256]@[256,1024]
        k_cvtA<<<(NN * HD + 255) / 256, 256>>>(A, pAh, pAl, NN * HD);
        k_cvtBT<<<(HD * 1024 + 255) / 256, 256>>>(gat_w + (size_t)l * 256 * 1024,
                                                  pBh, pBl, HD, 1024);
        k_mma<<<dim3(1024 / 128, MT), 256, GEMM_SMEM>>>(pAh, pAl, pBh, pBl, pxp,
                                                        NN, 1024, HD, nullptr, 0);

        k_attn2<<<NN, 128>>>(att_src + l * 1024, att_dst + l * 1024, l);
        k_smax<<<(EE + 255) / 256, 256>>>(src, dst, l);
        k_selfsum<<<(NN * 4 + 255) / 256, 256>>>();
        k_sexp<<<(EE + 255) / 256, 256>>>(dst);
        k_gather<<<NN, 256>>>(A, XO, gat_b + l * 256, ln_g + l * 256, ln_b + l * 256);
    }
    // after l=2, emb lives in px2

    // ---- 4 prediction heads: hmid = relu(emb @ W1 + b1)   [20000,256]@[256,128] ----
    k_cvtA<<<(NN * HD + 255) / 256, 256>>>(px2, pAh, pAl, NN * HD);
    for (int k = 0; k < 4; k++) {
        k_cvtBT<<<(HD * 128 + 255) / 256, 256>>>(head_w1 + (size_t)k * 256 * 128,
                                                 pBh, pBl, HD, 128);
        k_mma<<<dim3(128 / 128, MT), 256, GEMM_SMEM>>>(pAh, pAl, pBh, pBl,
                                                       phmid + (size_t)k * NN * 128,
                                                       NN, 128, HD, head_b1 + k * 128, 1);
    }
    k_headout<<<NN, 128>>>(head_w2, head_b2, out);
    if (out_size >= 4 * NN + NN * HD)
        k_emb<<<((size_t)NN * HD + 255) / 256, 256>>>(px2, out);
}

// round 6
// speedup vs baseline: 2.0347x; 1.1031x over previous
#include <cuda_runtime.h>
#include <cuda_bf16.h>
#include <cstdint>
#include <math.h>

#define NN 20000
#define EE 200000
#define HD 256
#define NHEADS 4
#define NDIM 128
#define EDIM 64
#define NL 3

// ---------------- scratch (static device globals; no runtime allocation) ----------------
__device__ float g_x  [(size_t)NN * HD];
__device__ float g_x2 [(size_t)NN * HD];
__device__ float g_xp [(size_t)NN * NHEADS * HD];   // [N, 4, 256] = [N,1024]
__device__ float g_as [NN * NHEADS];
__device__ float g_ad [NN * NHEADS];
__device__ float g_ew [NL * EE];
__device__ float g_loopw[NL * NN];
__device__ int   g_counts[NN];
__device__ int   g_cursor[NN];
__device__ int   g_rowptr[NN + 1];
__device__ int   g_csrc[EE];
__device__ int   g_ceid[EE];
__device__ float g_hmid[4 * (size_t)NN * (HD / 2)];
__device__ float g_wmean[NL * EDIM];
__device__ float g_bmean[NL];
__device__ float g_cvec [NL * NHEADS];
// bf16 split buffers for tensor-core GEMM
__device__ __nv_bfloat16 g_Ah[(size_t)NN * HD];   // encoder input split (node features)
__device__ __nv_bfloat16 g_Al[(size_t)NN * HD];
__device__ __nv_bfloat16 g_Xh[(size_t)NN * HD];   // activation split (x), produced by epilogues
__device__ __nv_bfloat16 g_Xl[(size_t)NN * HD];
__device__ __nv_bfloat16 g_Bh[1024 * 256];
__device__ __nv_bfloat16 g_Bl[1024 * 256];

// ---------------- helpers ----------------
__device__ __forceinline__ float lrelu(float x) { return fmaxf(x, 0.2f * x); }

__device__ __forceinline__ void mma16816(float* c, const uint32_t* a, const uint32_t* b) {
    asm volatile(
        "mma.sync.aligned.m16n8k16.row.col.f32.bf16.bf16.f32 "
        "{%0,%1,%2,%3}, {%4,%5,%6,%7}, {%8,%9}, {%0,%1,%2,%3};"
        : "+f"(c[0]), "+f"(c[1]), "+f"(c[2]), "+f"(c[3])
        : "r"(a[0]), "r"(a[1]), "r"(a[2]), "r"(a[3]), "r"(b[0]), "r"(b[1]));
}
__device__ __forceinline__ void ldsm4(uint32_t addr, uint32_t* r) {
    asm volatile("ldmatrix.sync.aligned.m8n8.x4.shared.b16 {%0,%1,%2,%3}, [%4];"
                 : "=r"(r[0]), "=r"(r[1]), "=r"(r[2]), "=r"(r[3]) : "r"(addr));
}
__device__ __forceinline__ void cpa16z(uint32_t dst, const void* src, int sz) {
    asm volatile("cp.async.cg.shared.global [%0], [%1], 16, %2;"
                 :: "r"(dst), "l"(src), "r"(sz));
}

// ---------------- bf16x3 GEMM, double-buffered cp.async pipeline ----------------
// C[M,N] = A[M,K]@B[K,N] (+bias)(+relu); A split [M,K] row-major; B split [N,K] row-major.
// Block 128x128, 8 warps (2Mx4N), warp 64x32, K-chunk 32, 2 stages.
#define KCH 32
#define AST 40                       // smem row stride bf16 (80B: conflict-free ldmatrix)
#define STG (128 * AST)              // elems per half-operand per stage
#define GEMM_SMEM (8 * STG * 2)      // 81920 bytes
__global__ __launch_bounds__(256, 2) void k_mma(
    const __nv_bfloat16* __restrict__ Ah, const __nv_bfloat16* __restrict__ Al,
    const __nv_bfloat16* __restrict__ Bh, const __nv_bfloat16* __restrict__ Bl,
    float* __restrict__ C, __nv_bfloat16* __restrict__ Chi, __nv_bfloat16* __restrict__ Clo,
    int M, int N, int K, const float* __restrict__ bias, int doRelu) {
    extern __shared__ __nv_bfloat16 sm[];
    uint32_t base = (uint32_t)__cvta_generic_to_shared(sm);

    int tid = threadIdx.x, lane = tid & 31, wid = tid >> 5;
    int nb = blockIdx.x, mb = blockIdx.y;
    int warpM = wid >> 2, warpN = wid & 3;
    int gid = lane >> 2, qid = lane & 3;
    int NC = K / KCH;

    // stage offsets in bytes
    auto offAh = [&](int s) { return base + (uint32_t)(2 * s) * STG * 2; };
    auto offAl = [&](int s) { return base + (uint32_t)(2 * s + 1) * STG * 2; };
    auto offBh = [&](int s) { return base + (uint32_t)(4 + 2 * s) * STG * 2; };
    auto offBl = [&](int s) { return base + (uint32_t)(5 + 2 * s) * STG * 2; };

    auto load_chunk = [&](int kc, int s) {
        int k0 = kc * KCH;
#pragma unroll
        for (int i = tid; i < 512; i += 256) {
            int row = i >> 2, c = i & 3;
            uint32_t so = (uint32_t)(row * AST + c * 8) * 2;
            int gr = mb * 128 + row;
            int sz = (gr < M) ? 16 : 0;
            int grc = (gr < M) ? gr : (M - 1);
            cpa16z(offAh(s) + so, Ah + (size_t)grc * K + k0 + c * 8, sz);
            cpa16z(offAl(s) + so, Al + (size_t)grc * K + k0 + c * 8, sz);
            int gn = nb * 128 + row;
            cpa16z(offBh(s) + so, Bh + (size_t)gn * K + k0 + c * 8, 16);
            cpa16z(offBl(s) + so, Bl + (size_t)gn * K + k0 + c * 8, 16);
        }
        asm volatile("cp.async.commit_group;");
    };

    float acc[4][4][4];
#pragma unroll
    for (int i = 0; i < 4; i++)
#pragma unroll
        for (int j = 0; j < 4; j++)
#pragma unroll
            for (int k = 0; k < 4; k++) acc[i][j][k] = 0.f;

    int aRow = (lane & 15), aCol = (lane >> 4) * 8;
    int bRow = (lane & 7) + ((lane >> 4) << 3), bCol = ((lane >> 3) & 1) * 8;

    load_chunk(0, 0);

    for (int kc = 0; kc < NC; kc++) {
        int s = kc & 1;
        if (kc + 1 < NC) {
            load_chunk(kc + 1, s ^ 1);
            asm volatile("cp.async.wait_group 1;" ::: "memory");
        } else {
            asm volatile("cp.async.wait_group 0;" ::: "memory");
        }
        __syncthreads();

#pragma unroll
        for (int ks = 0; ks < KCH; ks += 16) {
            uint32_t ah[4][4], al[4][4], bh[2][4], bl[2][4];
#pragma unroll
            for (int mt = 0; mt < 4; mt++) {
                uint32_t o = (uint32_t)((warpM * 64 + mt * 16 + aRow) * AST + ks + aCol) * 2;
                ldsm4(offAh(s) + o, ah[mt]);
                ldsm4(offAl(s) + o, al[mt]);
            }
#pragma unroll
            for (int np = 0; np < 2; np++) {
                uint32_t o = (uint32_t)((warpN * 32 + np * 16 + bRow) * AST + ks + bCol) * 2;
                ldsm4(offBh(s) + o, bh[np]);
                ldsm4(offBl(s) + o, bl[np]);
            }
#pragma unroll
            for (int mt = 0; mt < 4; mt++)
#pragma unroll
                for (int nt = 0; nt < 4; nt++) {
                    const uint32_t* bhp = &bh[nt >> 1][(nt & 1) * 2];
                    const uint32_t* blp = &bl[nt >> 1][(nt & 1) * 2];
                    mma16816(acc[mt][nt], ah[mt], bhp);
                    mma16816(acc[mt][nt], ah[mt], blp);
                    mma16816(acc[mt][nt], al[mt], bhp);
                }
        }
        __syncthreads();
    }

    // epilogue: c0:(gid,qid*2) c1:(gid,qid*2+1) c2:(gid+8,qid*2) c3:(gid+8,qid*2+1)
#pragma unroll
    for (int mt = 0; mt < 4; mt++) {
        int r0 = mb * 128 + warpM * 64 + mt * 16 + gid;
#pragma unroll
        for (int nt = 0; nt < 4; nt++) {
            int cn = nb * 128 + warpN * 32 + nt * 8 + qid * 2;
            float b0 = bias ? bias[cn] : 0.f;
            float b1 = bias ? bias[cn + 1] : 0.f;
#pragma unroll
            for (int half = 0; half < 2; half++) {
                int r = r0 + half * 8;
                if (r < M) {
                    float v0 = acc[mt][nt][half * 2 + 0] + b0;
                    float v1 = acc[mt][nt][half * 2 + 1] + b1;
                    if (doRelu) { v0 = fmaxf(v0, 0.f); v1 = fmaxf(v1, 0.f); }
                    size_t o = (size_t)r * N + cn;
                    C[o] = v0;
                    C[o + 1] = v1;
                    if (Chi) {
                        __nv_bfloat16 h0 = __float2bfloat16(v0);
                        __nv_bfloat16 h1 = __float2bfloat16(v1);
                        Chi[o] = h0;
                        Chi[o + 1] = h1;
                        Clo[o] = __float2bfloat16(v0 - __bfloat162float(h0));
                        Clo[o + 1] = __float2bfloat16(v1 - __bfloat162float(h1));
                    }
                }
            }
        }
    }
}

// ---------------- bf16 hi/lo split conversions ----------------
__global__ void k_cvtA(const float* __restrict__ in, __nv_bfloat16* __restrict__ hi,
                       __nv_bfloat16* __restrict__ lo, int n) {
    int i = blockIdx.x * 256 + threadIdx.x;
    if (i < n) {
        float v = in[i];
        __nv_bfloat16 h = __float2bfloat16(v);
        hi[i] = h;
        lo[i] = __float2bfloat16(v - __bfloat162float(h));
    }
}
__global__ void k_cvtBT(const float* __restrict__ in, __nv_bfloat16* __restrict__ hi,
                        __nv_bfloat16* __restrict__ lo, int K, int N) {
    int i = blockIdx.x * 256 + threadIdx.x;
    if (i < K * N) {
        int kk = i / N, n = i % N;
        float v = in[i];
        __nv_bfloat16 h = __float2bfloat16(v);
        size_t o = (size_t)n * K + kk;
        hi[o] = h;
        lo[o] = __float2bfloat16(v - __bfloat162float(h));
    }
}

// ---------------- preprocessing ----------------
__global__ void k_zero() {
    int i = blockIdx.x * 256 + threadIdx.x;
    if (i < NN) { g_counts[i] = 0; g_cursor[i] = 0; }
}
__global__ void k_count(const int* __restrict__ dst) {
    int e = blockIdx.x * 256 + threadIdx.x;
    if (e < EE) atomicAdd(&g_counts[dst[e]], 1);
}
__global__ void k_scan() {
    __shared__ int sh[1024];
    int tid = threadIdx.x;
    int carry = 0;
    for (int base = 0; base < NN; base += 1024) {
        int i = base + tid;
        int v = (i < NN) ? g_counts[i] : 0;
        sh[tid] = v;
        __syncthreads();
        for (int off = 1; off < 1024; off <<= 1) {
            int t = (tid >= off) ? sh[tid - off] : 0;
            __syncthreads();
            sh[tid] += t;
            __syncthreads();
        }
        if (i < NN) g_rowptr[i + 1] = carry + sh[tid];
        carry += sh[1023];
        __syncthreads();
    }
    if (tid == 0) g_rowptr[0] = 0;
}
__global__ void k_scatter(const int* __restrict__ src, const int* __restrict__ dst) {
    int e = blockIdx.x * 256 + threadIdx.x;
    if (e < EE) {
        int d = dst[e];
        int pos = g_rowptr[d] + atomicAdd(&g_cursor[d], 1);
        g_csrc[pos] = src[e];
        g_ceid[pos] = e;
    }
}
__global__ void k_wmean(const float* __restrict__ W) {
    __shared__ float red[256];
    int ld = blockIdx.x;
    red[threadIdx.x] = W[(size_t)ld * 256 + threadIdx.x];
    __syncthreads();
    for (int s = 128; s; s >>= 1) {
        if (threadIdx.x < s) red[threadIdx.x] += red[threadIdx.x + s];
        __syncthreads();
    }
    if (threadIdx.x == 0) g_wmean[ld] = red[0] * (1.f / 256.f);
}
__global__ void k_bmean(const float* __restrict__ b) {
    __shared__ float red[256];
    int l = blockIdx.x;
    red[threadIdx.x] = b[l * 256 + threadIdx.x];
    __syncthreads();
    for (int s = 128; s; s >>= 1) {
        if (threadIdx.x < s) red[threadIdx.x] += red[threadIdx.x + s];
        __syncthreads();
    }
    if (threadIdx.x == 0) g_bmean[l] = red[0] * (1.f / 256.f);
}
__global__ void k_cvec(const float* __restrict__ lew, const float* __restrict__ ae) {
    __shared__ float red[256];
    int lh = blockIdx.x;
    size_t off = (size_t)lh * 256 + threadIdx.x;
    red[threadIdx.x] = lew[off] * ae[off];
    __syncthreads();
    for (int s = 128; s; s >>= 1) {
        if (threadIdx.x < s) red[threadIdx.x] += red[threadIdx.x + s];
        __syncthreads();
    }
    if (threadIdx.x == 0) g_cvec[lh] = red[0];
}

// ew for ALL layers in one pass over edge_attr (warp per edge)
__global__ void k_ew3(const float* __restrict__ ea) {
    int warp = threadIdx.x >> 5, lane = threadIdx.x & 31;
    int e = blockIdx.x * 8 + warp;
    if (e >= EE) return;
    const float* row = ea + (size_t)e * EDIM;
    float v0 = row[lane], v1 = row[lane + 32];
    float s0 = v0 * g_wmean[lane] + v1 * g_wmean[lane + 32];
    float s1 = v0 * g_wmean[64 + lane] + v1 * g_wmean[64 + lane + 32];
    float s2 = v0 * g_wmean[128 + lane] + v1 * g_wmean[128 + lane + 32];
    for (int o = 16; o; o >>= 1) {
        s0 += __shfl_down_sync(0xffffffff, s0, o);
        s1 += __shfl_down_sync(0xffffffff, s1, o);
        s2 += __shfl_down_sync(0xffffffff, s2, o);
    }
    if (lane == 0) {
        g_ew[e] = s0 + g_bmean[0];
        g_ew[EE + e] = s1 + g_bmean[1];
        g_ew[2 * EE + e] = s2 + g_bmean[2];
    }
}

__global__ void k_loopw3() {
    int n = blockIdx.x * 256 + threadIdx.x;
    if (n < NN) {
        int b = g_rowptr[n], e = g_rowptr[n + 1];
        float s0 = 0.f, s1 = 0.f, s2 = 0.f;
        for (int p = b; p < e; p++) {
            int id = g_ceid[p];
            s0 += g_ew[id];
            s1 += g_ew[EE + id];
            s2 += g_ew[2 * EE + id];
        }
        float inv = 1.f / fmaxf((float)(e - b), 1.f);
        g_loopw[n] = s0 * inv;
        g_loopw[NN + n] = s1 * inv;
        g_loopw[2 * NN + n] = s2 * inv;
    }
}

// ---------------- attention scores (warp per head) ----------------
__global__ void k_attn2(const float* __restrict__ att_s, const float* __restrict__ att_d) {
    int n = blockIdx.x;
    int warp = threadIdx.x >> 5, lane = threadIdx.x & 31;
    const float* xr = g_xp + (size_t)n * 1024 + warp * 256;
    const float* as = att_s + warp * 256;
    const float* ad = att_d + warp * 256;
    float s = 0.f, d = 0.f;
    for (int i = lane; i < 256; i += 32) {
        float v = xr[i];
        s += v * as[i];
        d += v * ad[i];
    }
    for (int o = 16; o; o >>= 1) {
        s += __shfl_down_sync(0xffffffff, s, o);
        d += __shfl_down_sync(0xffffffff, d, o);
    }
    if (lane == 0) {
        g_as[n * 4 + warp] = s;
        g_ad[n * 4 + warp] = d;
    }
}

// ---------------- fused GAT: online softmax + gather + bias + LN + residual + bf16 split ----------------
#define GCH 128
__global__ __launch_bounds__(256) void k_gather(const float* __restrict__ x,
                                                float* __restrict__ xo,
                                                __nv_bfloat16* __restrict__ xh,
                                                __nv_bfloat16* __restrict__ xl,
                                                int l,
                                                const float* __restrict__ gat_b,
                                                const float* __restrict__ ln_g,
                                                const float* __restrict__ ln_b) {
    int n = blockIdx.x, tid = threadIdx.x;
    int lane = tid & 31, wid = tid >> 5;
    int head = tid >> 6, f4 = tid & 63;
    __shared__ int ssrc[GCH];
    __shared__ float slog[GCH][4];
    __shared__ float wt[GCH][4];
    __shared__ float sm4[4], ss4[4], sf4[4];
    __shared__ float sred[1024];
    __shared__ float sw[8];
    __shared__ float sMu, sVar;

    int beg = g_rowptr[n];
    int deg = g_rowptr[n + 1] - beg;

    float4 adv = *(const float4*)&g_ad[n * 4];
    float4 cv = *(const float4*)&g_cvec[l * 4];
    float lw = g_loopw[l * NN + n];
    if (tid < 4) {
        float sl = lrelu(g_as[n * 4 + tid] + g_ad[n * 4 + tid] + lw * g_cvec[l * 4 + tid]);
        sm4[tid] = sl;
        ss4[tid] = 1.f;
    }
    __syncthreads();

    const float4* xp4 = (const float4*)g_xp;
    float4 acc = xp4[(size_t)n * 256 + head * 64 + f4];  // self, weight 1 at current max

    for (int ch = 0; ch < deg; ch += GCH) {
        int cnt = min(GCH, deg - ch);
        if (tid < cnt) {
            int p = beg + ch + tid;
            int s0 = g_csrc[p];
            float w = g_ew[l * EE + g_ceid[p]];
            ssrc[tid] = s0;
            float4 as4 = *(const float4*)&g_as[s0 * 4];
            slog[tid][0] = lrelu(as4.x + adv.x + w * cv.x);
            slog[tid][1] = lrelu(as4.y + adv.y + w * cv.y);
            slog[tid][2] = lrelu(as4.z + adv.z + w * cv.z);
            slog[tid][3] = lrelu(as4.w + adv.w + w * cv.w);
        }
        __syncthreads();
        if (wid < 4) {
            int h = wid;
            float cm = -1e30f;
            for (int j = lane; j < cnt; j += 32) cm = fmaxf(cm, slog[j][h]);
            for (int o = 16; o; o >>= 1) cm = fmaxf(cm, __shfl_xor_sync(0xffffffff, cm, o));
            float mold = sm4[h];
            float mnew = fmaxf(mold, cm);
            float fac = expf(mold - mnew);
            float cs = 0.f;
            for (int j = lane; j < cnt; j += 32) {
                float p = expf(slog[j][h] - mnew);
                wt[j][h] = p;
                cs += p;
            }
            for (int o = 16; o; o >>= 1) cs += __shfl_xor_sync(0xffffffff, cs, o);
            if (lane == 0) {
                ss4[h] = ss4[h] * fac + cs;
                sm4[h] = mnew;
                sf4[h] = fac;
            }
        }
        __syncthreads();
        float f = sf4[head];
        acc.x *= f; acc.y *= f; acc.z *= f; acc.w *= f;
        for (int j = 0; j < cnt; j++) {
            float a = wt[j][head];
            float4 v = xp4[(size_t)ssrc[j] * 256 + head * 64 + f4];
            acc.x += a * v.x;
            acc.y += a * v.y;
            acc.z += a * v.z;
            acc.w += a * v.w;
        }
        __syncthreads();   // before smem reuse next chunk
    }

    float inv = 0.25f / ss4[head];
    acc.x *= inv; acc.y *= inv; acc.z *= inv; acc.w *= inv;
    *(float4*)&sred[head * 256 + f4 * 4] = acc;
    __syncthreads();

    float h = sred[tid] + sred[256 + tid] + sred[512 + tid] + sred[768 + tid] + gat_b[tid];

    float v = h;
    for (int o = 16; o; o >>= 1) v += __shfl_xor_sync(0xffffffff, v, o);
    if (lane == 0) sw[wid] = v;
    __syncthreads();
    if (tid == 0) {
        float t = sw[0] + sw[1] + sw[2] + sw[3] + sw[4] + sw[5] + sw[6] + sw[7];
        sMu = t * (1.f / 256.f);
    }
    __syncthreads();
    float mu = sMu;
    float df = h - mu;
    v = df * df;
    for (int o = 16; o; o >>= 1) v += __shfl_xor_sync(0xffffffff, v, o);
    __syncthreads();
    if (lane == 0) sw[wid] = v;
    __syncthreads();
    if (tid == 0) {
        float t = sw[0] + sw[1] + sw[2] + sw[3] + sw[4] + sw[5] + sw[6] + sw[7];
        sVar = t * (1.f / 256.f);
    }
    __syncthreads();
    float y = ln_g[tid] * df * rsqrtf(sVar + 1e-5f) + ln_b[tid];
    size_t idx = (size_t)n * 256 + tid;
    float o = fmaxf(x[idx] + y, 0.f);
    xo[idx] = o;
    __nv_bfloat16 bh = __float2bfloat16(o);
    xh[idx] = bh;
    xl[idx] = __float2bfloat16(o - __bfloat162float(bh));
}

// ---------------- prediction heads epilogue ----------------
__global__ void k_headout(const float* __restrict__ w2, const float* __restrict__ b2,
                          float* __restrict__ out) {
    int n = blockIdx.x;
    int k = threadIdx.x >> 5, lane = threadIdx.x & 31;
    const float* hr = g_hmid + ((size_t)k * NN + n) * 128;
    const float* w = w2 + k * 128;
    float s = 0.f;
    for (int i = lane; i < 128; i += 32) s += hr[i] * w[i];
    for (int o = 16; o; o >>= 1) s += __shfl_down_sync(0xffffffff, s, o);
    if (lane == 0) {
        float v = s + b2[k];
        if (k == 0 || k == 3) v = 1.f / (1.f + expf(-v));
        out[(size_t)k * NN + n] = v;
    }
}

__global__ void k_emb(const float* __restrict__ emb, float* __restrict__ out) {
    size_t i = (size_t)blockIdx.x * 256 + threadIdx.x;
    if (i < (size_t)NN * HD) out[(size_t)4 * NN + i] = emb[i];
}

// ---------------- launch ----------------
extern "C" void kernel_launch(void* const* d_in, const int* in_sizes, int n_in,
                              void* d_out, int out_size) {
    const float* node_features = (const float*)d_in[0];
    const float* edge_attr     = (const float*)d_in[1];
    const float* enc_w         = (const float*)d_in[2];
    const float* enc_b         = (const float*)d_in[3];
    const float* edge_enc_w    = (const float*)d_in[4];
    const float* edge_enc_b    = (const float*)d_in[5];
    const float* gat_w         = (const float*)d_in[6];
    const float* att_src       = (const float*)d_in[7];
    const float* att_dst       = (const float*)d_in[8];
    const float* att_edge      = (const float*)d_in[9];
    const float* lin_edge_w    = (const float*)d_in[10];
    const float* gat_b         = (const float*)d_in[11];
    const float* ln_g          = (const float*)d_in[12];
    const float* ln_b          = (const float*)d_in[13];
    const float* head_w1       = (const float*)d_in[14];
    const float* head_b1       = (const float*)d_in[15];
    const float* head_w2       = (const float*)d_in[16];
    const float* head_b2       = (const float*)d_in[17];
    const int*   src           = (const int*)d_in[18];
    const int*   dst           = src + EE;
    float* out = (float*)d_out;

    float *px, *px2, *pxp, *phmid;
    __nv_bfloat16 *pAh, *pAl, *pXh, *pXl, *pBh, *pBl;
    cudaGetSymbolAddress((void**)&px, g_x);
    cudaGetSymbolAddress((void**)&px2, g_x2);
    cudaGetSymbolAddress((void**)&pxp, g_xp);
    cudaGetSymbolAddress((void**)&phmid, g_hmid);
    cudaGetSymbolAddress((void**)&pAh, g_Ah);
    cudaGetSymbolAddress((void**)&pAl, g_Al);
    cudaGetSymbolAddress((void**)&pXh, g_Xh);
    cudaGetSymbolAddress((void**)&pXl, g_Xl);
    cudaGetSymbolAddress((void**)&pBh, g_Bh);
    cudaGetSymbolAddress((void**)&pBl, g_Bl);

    cudaFuncSetAttribute(k_mma, cudaFuncAttributeMaxDynamicSharedMemorySize, GEMM_SMEM);

    const int MT = (NN + 127) / 128;  // 157 M-tiles

    // ---- graph preprocessing (dst-CSR) + per-layer constants ----
    k_zero<<<(NN + 255) / 256, 256>>>();
    k_count<<<(EE + 255) / 256, 256>>>(dst);
    k_scan<<<1, 1024>>>();
    k_scatter<<<(EE + 255) / 256, 256>>>(src, dst);
    k_wmean<<<NL * EDIM, 256>>>(edge_enc_w);
    k_bmean<<<NL, 256>>>(edge_enc_b);
    k_cvec<<<NL * NHEADS, 256>>>(lin_edge_w, att_edge);
    k_ew3<<<(EE + 7) / 8, 256>>>(edge_attr);
    k_loopw3<<<(NN + 255) / 256, 256>>>();

    // ---- encoder: x = relu(nf @ enc_w + enc_b), emits fp32 + bf16 split ----
    k_cvtA<<<(NN * NDIM + 255) / 256, 256>>>(node_features, pAh, pAl, NN * NDIM);
    k_cvtBT<<<(NDIM * HD + 255) / 256, 256>>>(enc_w, pBh, pBl, NDIM, HD);
    k_mma<<<dim3(HD / 128, MT), 256, GEMM_SMEM>>>(pAh, pAl, pBh, pBl, px, pXh, pXl,
                                                  NN, HD, NDIM, enc_b, 1);

    // ---- 3 GAT layers ----
    for (int l = 0; l < NL; l++) {
        const float* A = (l & 1) ? px2 : px;
        float* XO      = (l & 1) ? px  : px2;

        // xp = x @ gat_w[l]   [20000,256]@[256,1024]
        k_cvtBT<<<(HD * 1024 + 255) / 256, 256>>>(gat_w + (size_t)l * 256 * 1024,
                                                  pBh, pBl, HD, 1024);
        k_mma<<<dim3(1024 / 128, MT), 256, GEMM_SMEM>>>(pXh, pXl, pBh, pBl, pxp,
                                                        nullptr, nullptr,
                                                        NN, 1024, HD, nullptr, 0);

        k_attn2<<<NN, 128>>>(att_src + l * 1024, att_dst + l * 1024);
        k_gather<<<NN, 256>>>(A, XO, pXh, pXl, l,
                              gat_b + l * 256, ln_g + l * 256, ln_b + l * 256);
    }
    // after l=2, emb lives in px2; its bf16 split in pXh/pXl

    // ---- 4 prediction heads: hmid = relu(emb @ W1 + b1) ----
    for (int k = 0; k < 4; k++) {
        k_cvtBT<<<(HD * 128 + 255) / 256, 256>>>(head_w1 + (size_t)k * 256 * 128,
                                                 pBh, pBl, HD, 128);
        k_mma<<<dim3(128 / 128, MT), 256, GEMM_SMEM>>>(pXh, pXl, pBh, pBl,
                                                       phmid + (size_t)k * NN * 128,
                                                       nullptr, nullptr,
                                                       NN, 128, HD, head_b1 + k * 128, 1);
    }
    k_headout<<<NN, 128>>>(head_w2, head_b2, out);
    if (out_size >= 4 * NN + NN * HD)
        k_emb<<<((size_t)NN * HD + 255) / 256, 256>>>(px2, out);
}

// round 7
// speedup vs baseline: 2.2260x; 1.0940x over previous
#include <cuda_runtime.h>
#include <cuda_bf16.h>
#include <cstdint>
#include <math.h>

#define NN 20000
#define EE 200000
#define HD 256
#define NHEADS 4
#define NDIM 128
#define EDIM 64
#define NL 3

// ---------------- scratch (static device globals; no runtime allocation) ----------------
__device__ float g_x  [(size_t)NN * HD];
__device__ float g_x2 [(size_t)NN * HD];
__device__ float g_xp [(size_t)NN * NHEADS * HD];   // [N, 4, 256] = [N,1024]
__device__ float g_as [NN * NHEADS];
__device__ float g_ad [NN * NHEADS];
__device__ float g_ew [NL * EE];
__device__ float g_loopw[NL * NN];
__device__ int   g_counts[NN];
__device__ int   g_cursor[NN];
__device__ int   g_rowptr[NN + 1];
__device__ int   g_csrc[EE];
__device__ int   g_ceid[EE];
__device__ float g_hmid[(size_t)NN * 512];
__device__ float g_wmean[NL * EDIM];
__device__ float g_bmean[NL];
__device__ float g_cvec [NL * NHEADS];
// bf16 split buffers for tensor-core GEMM
__device__ __nv_bfloat16 g_Ah[(size_t)NN * HD];   // encoder input split (node features)
__device__ __nv_bfloat16 g_Al[(size_t)NN * HD];
__device__ __nv_bfloat16 g_Xh[(size_t)NN * HD];   // activation split (x), produced by epilogues
__device__ __nv_bfloat16 g_Xl[(size_t)NN * HD];
__device__ __nv_bfloat16 g_Bh[1024 * 256];
__device__ __nv_bfloat16 g_Bl[1024 * 256];

// ---------------- helpers ----------------
__device__ __forceinline__ float lrelu(float x) { return fmaxf(x, 0.2f * x); }

__device__ __forceinline__ void mma16816(float* c, const uint32_t* a, const uint32_t* b) {
    asm volatile(
        "mma.sync.aligned.m16n8k16.row.col.f32.bf16.bf16.f32 "
        "{%0,%1,%2,%3}, {%4,%5,%6,%7}, {%8,%9}, {%0,%1,%2,%3};"
        : "+f"(c[0]), "+f"(c[1]), "+f"(c[2]), "+f"(c[3])
        : "r"(a[0]), "r"(a[1]), "r"(a[2]), "r"(a[3]), "r"(b[0]), "r"(b[1]));
}
__device__ __forceinline__ void ldsm4(uint32_t addr, uint32_t* r) {
    asm volatile("ldmatrix.sync.aligned.m8n8.x4.shared.b16 {%0,%1,%2,%3}, [%4];"
                 : "=r"(r[0]), "=r"(r[1]), "=r"(r[2]), "=r"(r[3]) : "r"(addr));
}
__device__ __forceinline__ void cpa16z(uint32_t dst, const void* src, int sz) {
    asm volatile("cp.async.cg.shared.global [%0], [%1], 16, %2;"
                 :: "r"(dst), "l"(src), "r"(sz));
}

// ---------------- bf16x3 GEMM, double-buffered cp.async pipeline ----------------
// C[M,N] = A[M,K]@B[K,N] (+bias)(+relu); A split [M,K] row-major; B split [N,K] row-major.
// Block 128x128, 8 warps (2Mx4N), warp 64x32, K-chunk 32, 2 stages.
// Optional fused epilogues: bf16 hi/lo re-split (Chi/Clo) and attention dots (attS/attD).
#define KCH 32
#define AST 40                       // smem row stride bf16 (80B: conflict-free ldmatrix)
#define STG (128 * AST)              // elems per half-operand per stage
#define GEMM_SMEM (8 * STG * 2)      // 81920 bytes
__global__ __launch_bounds__(256, 2) void k_mma(
    const __nv_bfloat16* __restrict__ Ah, const __nv_bfloat16* __restrict__ Al,
    const __nv_bfloat16* __restrict__ Bh, const __nv_bfloat16* __restrict__ Bl,
    float* __restrict__ C, __nv_bfloat16* __restrict__ Chi, __nv_bfloat16* __restrict__ Clo,
    int M, int N, int K, const float* __restrict__ bias, int doRelu,
    const float* __restrict__ attS, const float* __restrict__ attD) {
    extern __shared__ __nv_bfloat16 sm[];
    __shared__ float sAS[128], sAD[128];
    uint32_t base = (uint32_t)__cvta_generic_to_shared(sm);

    int tid = threadIdx.x, lane = tid & 31, wid = tid >> 5;
    int nb = blockIdx.x, mb = blockIdx.y;
    int warpM = wid >> 2, warpN = wid & 3;
    int gid = lane >> 2, qid = lane & 3;
    int NC = K / KCH;

    auto offAh = [&](int s) { return base + (uint32_t)(2 * s) * STG * 2; };
    auto offAl = [&](int s) { return base + (uint32_t)(2 * s + 1) * STG * 2; };
    auto offBh = [&](int s) { return base + (uint32_t)(4 + 2 * s) * STG * 2; };
    auto offBl = [&](int s) { return base + (uint32_t)(5 + 2 * s) * STG * 2; };

    auto load_chunk = [&](int kc, int s) {
        int k0 = kc * KCH;
#pragma unroll
        for (int i = tid; i < 512; i += 256) {
            int row = i >> 2, c = i & 3;
            uint32_t so = (uint32_t)(row * AST + c * 8) * 2;
            int gr = mb * 128 + row;
            int sz = (gr < M) ? 16 : 0;
            int grc = (gr < M) ? gr : (M - 1);
            cpa16z(offAh(s) + so, Ah + (size_t)grc * K + k0 + c * 8, sz);
            cpa16z(offAl(s) + so, Al + (size_t)grc * K + k0 + c * 8, sz);
            int gn = nb * 128 + row;
            cpa16z(offBh(s) + so, Bh + (size_t)gn * K + k0 + c * 8, 16);
            cpa16z(offBl(s) + so, Bl + (size_t)gn * K + k0 + c * 8, 16);
        }
        asm volatile("cp.async.commit_group;");
    };

    float acc[4][4][4];
#pragma unroll
    for (int i = 0; i < 4; i++)
#pragma unroll
        for (int j = 0; j < 4; j++)
#pragma unroll
            for (int k = 0; k < 4; k++) acc[i][j][k] = 0.f;

    int aRow = (lane & 15), aCol = (lane >> 4) * 8;
    int bRow = (lane & 7) + ((lane >> 4) << 3), bCol = ((lane >> 3) & 1) * 8;

    load_chunk(0, 0);

    for (int kc = 0; kc < NC; kc++) {
        int s = kc & 1;
        if (kc + 1 < NC) {
            load_chunk(kc + 1, s ^ 1);
            asm volatile("cp.async.wait_group 1;" ::: "memory");
        } else {
            asm volatile("cp.async.wait_group 0;" ::: "memory");
        }
        __syncthreads();

#pragma unroll
        for (int ks = 0; ks < KCH; ks += 16) {
            uint32_t ah[4][4], al[4][4], bh[2][4], bl[2][4];
#pragma unroll
            for (int mt = 0; mt < 4; mt++) {
                uint32_t o = (uint32_t)((warpM * 64 + mt * 16 + aRow) * AST + ks + aCol) * 2;
                ldsm4(offAh(s) + o, ah[mt]);
                ldsm4(offAl(s) + o, al[mt]);
            }
#pragma unroll
            for (int np = 0; np < 2; np++) {
                uint32_t o = (uint32_t)((warpN * 32 + np * 16 + bRow) * AST + ks + bCol) * 2;
                ldsm4(offBh(s) + o, bh[np]);
                ldsm4(offBl(s) + o, bl[np]);
            }
#pragma unroll
            for (int mt = 0; mt < 4; mt++)
#pragma unroll
                for (int nt = 0; nt < 4; nt++) {
                    const uint32_t* bhp = &bh[nt >> 1][(nt & 1) * 2];
                    const uint32_t* blp = &bl[nt >> 1][(nt & 1) * 2];
                    mma16816(acc[mt][nt], ah[mt], bhp);
                    mma16816(acc[mt][nt], ah[mt], blp);
                    mma16816(acc[mt][nt], al[mt], bhp);
                }
        }
        __syncthreads();
    }

    // ---- fused attention dots: a_s[r,h] += sum_cn acc(r,cn)*attS[cn] (CTA covers 1 head) ----
    if (attS) {
        if (tid < 128) { sAS[tid] = 0.f; sAD[tid] = 0.f; }
        __syncthreads();
        float avS[8], avD[8];
#pragma unroll
        for (int nt = 0; nt < 4; nt++) {
            int cn = nb * 128 + warpN * 32 + nt * 8 + qid * 2;
            avS[nt * 2] = attS[cn];
            avS[nt * 2 + 1] = attS[cn + 1];
            avD[nt * 2] = attD[cn];
            avD[nt * 2 + 1] = attD[cn + 1];
        }
#pragma unroll
        for (int mt = 0; mt < 4; mt++)
#pragma unroll
            for (int half = 0; half < 2; half++) {
                float sp = 0.f, dp = 0.f;
#pragma unroll
                for (int nt = 0; nt < 4; nt++) {
                    float a0 = acc[mt][nt][half * 2], a1 = acc[mt][nt][half * 2 + 1];
                    sp += a0 * avS[nt * 2] + a1 * avS[nt * 2 + 1];
                    dp += a0 * avD[nt * 2] + a1 * avD[nt * 2 + 1];
                }
                sp += __shfl_xor_sync(0xffffffffu, sp, 1);
                sp += __shfl_xor_sync(0xffffffffu, sp, 2);
                dp += __shfl_xor_sync(0xffffffffu, dp, 1);
                dp += __shfl_xor_sync(0xffffffffu, dp, 2);
                if (qid == 0) {
                    int rl = warpM * 64 + mt * 16 + gid + half * 8;
                    atomicAdd(&sAS[rl], sp);
                    atomicAdd(&sAD[rl], dp);
                }
            }
        __syncthreads();
        if (tid < 128) {
            int r = mb * 128 + tid;
            if (r < M) {
                int h = nb >> 1;   // 128 cols/CTA, 256 cols/head
                atomicAdd(&g_as[r * 4 + h], sAS[tid]);
                atomicAdd(&g_ad[r * 4 + h], sAD[tid]);
            }
        }
    }

    // ---- C stores ----
#pragma unroll
    for (int mt = 0; mt < 4; mt++) {
        int r0 = mb * 128 + warpM * 64 + mt * 16 + gid;
#pragma unroll
        for (int nt = 0; nt < 4; nt++) {
            int cn = nb * 128 + warpN * 32 + nt * 8 + qid * 2;
            float b0 = bias ? bias[cn] : 0.f;
            float b1 = bias ? bias[cn + 1] : 0.f;
#pragma unroll
            for (int half = 0; half < 2; half++) {
                int r = r0 + half * 8;
                if (r < M) {
                    float v0 = acc[mt][nt][half * 2 + 0] + b0;
                    float v1 = acc[mt][nt][half * 2 + 1] + b1;
                    if (doRelu) { v0 = fmaxf(v0, 0.f); v1 = fmaxf(v1, 0.f); }
                    size_t o = (size_t)r * N + cn;
                    C[o] = v0;
                    C[o + 1] = v1;
                    if (Chi) {
                        __nv_bfloat16 h0 = __float2bfloat16(v0);
                        __nv_bfloat16 h1 = __float2bfloat16(v1);
                        Chi[o] = h0;
                        Chi[o + 1] = h1;
                        Clo[o] = __float2bfloat16(v0 - __bfloat162float(h0));
                        Clo[o + 1] = __float2bfloat16(v1 - __bfloat162float(h1));
                    }
                }
            }
        }
    }
}

// ---------------- bf16 hi/lo split conversions ----------------
__global__ void k_cvtA(const float* __restrict__ in, __nv_bfloat16* __restrict__ hi,
                       __nv_bfloat16* __restrict__ lo, int n) {
    int i = blockIdx.x * 256 + threadIdx.x;
    if (i < n) {
        float v = in[i];
        __nv_bfloat16 h = __float2bfloat16(v);
        hi[i] = h;
        lo[i] = __float2bfloat16(v - __bfloat162float(h));
    }
}
__global__ void k_cvtBT(const float* __restrict__ in, __nv_bfloat16* __restrict__ hi,
                        __nv_bfloat16* __restrict__ lo, int K, int N) {
    int i = blockIdx.x * 256 + threadIdx.x;
    if (i < K * N) {
        int kk = i / N, n = i % N;
        float v = in[i];
        __nv_bfloat16 h = __float2bfloat16(v);
        size_t o = (size_t)n * K + kk;
        hi[o] = h;
        lo[o] = __float2bfloat16(v - __bfloat162float(h));
    }
}
// head_w1 [4][256][128] -> combined B [512][256] K-contiguous split
__global__ void k_cvtHW(const float* __restrict__ in, __nv_bfloat16* __restrict__ hi,
                        __nv_bfloat16* __restrict__ lo) {
    int i = blockIdx.x * 256 + threadIdx.x;   // over 512*256
    if (i < 512 * 256) {
        int n = i >> 8, kk = i & 255;
        float v = in[(n >> 7) * 32768 + kk * 128 + (n & 127)];
        __nv_bfloat16 h = __float2bfloat16(v);
        hi[i] = h;
        lo[i] = __float2bfloat16(v - __bfloat162float(h));
    }
}
__global__ void k_zeroAS() {
    int i = blockIdx.x * 256 + threadIdx.x;
    if (i < NN * 4) { g_as[i] = 0.f; g_ad[i] = 0.f; }
}

// ---------------- preprocessing ----------------
__global__ void k_zero() {
    int i = blockIdx.x * 256 + threadIdx.x;
    if (i < NN) { g_counts[i] = 0; g_cursor[i] = 0; }
}
__global__ void k_count(const int* __restrict__ dst) {
    int e = blockIdx.x * 256 + threadIdx.x;
    if (e < EE) atomicAdd(&g_counts[dst[e]], 1);
}
__global__ void k_scan() {
    __shared__ int sh[1024];
    int tid = threadIdx.x;
    int carry = 0;
    for (int base = 0; base < NN; base += 1024) {
        int i = base + tid;
        int v = (i < NN) ? g_counts[i] : 0;
        sh[tid] = v;
        __syncthreads();
        for (int off = 1; off < 1024; off <<= 1) {
            int t = (tid >= off) ? sh[tid - off] : 0;
            __syncthreads();
            sh[tid] += t;
            __syncthreads();
        }
        if (i < NN) g_rowptr[i + 1] = carry + sh[tid];
        carry += sh[1023];
        __syncthreads();
    }
    if (tid == 0) g_rowptr[0] = 0;
}
__global__ void k_scatter(const int* __restrict__ src, const int* __restrict__ dst) {
    int e = blockIdx.x * 256 + threadIdx.x;
    if (e < EE) {
        int d = dst[e];
        int pos = g_rowptr[d] + atomicAdd(&g_cursor[d], 1);
        g_csrc[pos] = src[e];
        g_ceid[pos] = e;
    }
}
__global__ void k_wmean(const float* __restrict__ W) {
    __shared__ float red[256];
    int ld = blockIdx.x;
    red[threadIdx.x] = W[(size_t)ld * 256 + threadIdx.x];
    __syncthreads();
    for (int s = 128; s; s >>= 1) {
        if (threadIdx.x < s) red[threadIdx.x] += red[threadIdx.x + s];
        __syncthreads();
    }
    if (threadIdx.x == 0) g_wmean[ld] = red[0] * (1.f / 256.f);
}
__global__ void k_bmean(const float* __restrict__ b) {
    __shared__ float red[256];
    int l = blockIdx.x;
    red[threadIdx.x] = b[l * 256 + threadIdx.x];
    __syncthreads();
    for (int s = 128; s; s >>= 1) {
        if (threadIdx.x < s) red[threadIdx.x] += red[threadIdx.x + s];
        __syncthreads();
    }
    if (threadIdx.x == 0) g_bmean[l] = red[0] * (1.f / 256.f);
}
__global__ void k_cvec(const float* __restrict__ lew, const float* __restrict__ ae) {
    __shared__ float red[256];
    int lh = blockIdx.x;
    size_t off = (size_t)lh * 256 + threadIdx.x;
    red[threadIdx.x] = lew[off] * ae[off];
    __syncthreads();
    for (int s = 128; s; s >>= 1) {
        if (threadIdx.x < s) red[threadIdx.x] += red[threadIdx.x + s];
        __syncthreads();
    }
    if (threadIdx.x == 0) g_cvec[lh] = red[0];
}

// ew for ALL layers in one pass over edge_attr (warp per edge)
__global__ void k_ew3(const float* __restrict__ ea) {
    int warp = threadIdx.x >> 5, lane = threadIdx.x & 31;
    int e = blockIdx.x * 8 + warp;
    if (e >= EE) return;
    const float* row = ea + (size_t)e * EDIM;
    float v0 = row[lane], v1 = row[lane + 32];
    float s0 = v0 * g_wmean[lane] + v1 * g_wmean[lane + 32];
    float s1 = v0 * g_wmean[64 + lane] + v1 * g_wmean[64 + lane + 32];
    float s2 = v0 * g_wmean[128 + lane] + v1 * g_wmean[128 + lane + 32];
    for (int o = 16; o; o >>= 1) {
        s0 += __shfl_down_sync(0xffffffff, s0, o);
        s1 += __shfl_down_sync(0xffffffff, s1, o);
        s2 += __shfl_down_sync(0xffffffff, s2, o);
    }
    if (lane == 0) {
        g_ew[e] = s0 + g_bmean[0];
        g_ew[EE + e] = s1 + g_bmean[1];
        g_ew[2 * EE + e] = s2 + g_bmean[2];
    }
}

__global__ void k_loopw3() {
    int n = blockIdx.x * 256 + threadIdx.x;
    if (n < NN) {
        int b = g_rowptr[n], e = g_rowptr[n + 1];
        float s0 = 0.f, s1 = 0.f, s2 = 0.f;
        for (int p = b; p < e; p++) {
            int id = g_ceid[p];
            s0 += g_ew[id];
            s1 += g_ew[EE + id];
            s2 += g_ew[2 * EE + id];
        }
        float inv = 1.f / fmaxf((float)(e - b), 1.f);
        g_loopw[n] = s0 * inv;
        g_loopw[NN + n] = s1 * inv;
        g_loopw[2 * NN + n] = s2 * inv;
    }
}

// ---------------- fused GAT: online softmax + gather + bias + LN + residual + bf16 split ----------------
#define GCH 128
__global__ __launch_bounds__(256) void k_gather(const float* __restrict__ x,
                                                float* __restrict__ xo,
                                                __nv_bfloat16* __restrict__ xh,
                                                __nv_bfloat16* __restrict__ xl,
                                                int l,
                                                const float* __restrict__ gat_b,
                                                const float* __restrict__ ln_g,
                                                const float* __restrict__ ln_b) {
    int n = blockIdx.x, tid = threadIdx.x;
    int lane = tid & 31, wid = tid >> 5;
    int head = tid >> 6, f4 = tid & 63;
    __shared__ int ssrc[GCH];
    __shared__ float slog[GCH][4];
    __shared__ float wt[GCH][4];
    __shared__ float sm4[4], ss4[4], sf4[4];
    __shared__ float sred[1024];
    __shared__ float sw[8];
    __shared__ float sMu, sVar;

    int beg = g_rowptr[n];
    int deg = g_rowptr[n + 1] - beg;

    float4 adv = *(const float4*)&g_ad[n * 4];
    float4 cv = *(const float4*)&g_cvec[l * 4];
    float lw = g_loopw[l * NN + n];
    if (tid < 4) {
        float sl = lrelu(g_as[n * 4 + tid] + g_ad[n * 4 + tid] + lw * g_cvec[l * 4 + tid]);
        sm4[tid] = sl;
        ss4[tid] = 1.f;
    }
    __syncthreads();

    const float4* xp4 = (const float4*)g_xp;
    float4 acc = xp4[(size_t)n * 256 + head * 64 + f4];  // self, weight 1 at current max

    for (int ch = 0; ch < deg; ch += GCH) {
        int cnt = min(GCH, deg - ch);
        if (tid < cnt) {
            int p = beg + ch + tid;
            int s0 = g_csrc[p];
            float w = g_ew[l * EE + g_ceid[p]];
            ssrc[tid] = s0;
            float4 as4 = *(const float4*)&g_as[s0 * 4];
            slog[tid][0] = lrelu(as4.x + adv.x + w * cv.x);
            slog[tid][1] = lrelu(as4.y + adv.y + w * cv.y);
            slog[tid][2] = lrelu(as4.z + adv.z + w * cv.z);
            slog[tid][3] = lrelu(as4.w + adv.w + w * cv.w);
        }
        __syncthreads();
        if (wid < 4) {
            int h = wid;
            float cm = -1e30f;
            for (int j = lane; j < cnt; j += 32) cm = fmaxf(cm, slog[j][h]);
            for (int o = 16; o; o >>= 1) cm = fmaxf(cm, __shfl_xor_sync(0xffffffff, cm, o));
            float mold = sm4[h];
            float mnew = fmaxf(mold, cm);
            float fac = expf(mold - mnew);
            float cs = 0.f;
            for (int j = lane; j < cnt; j += 32) {
                float p = expf(slog[j][h] - mnew);
                wt[j][h] = p;
                cs += p;
            }
            for (int o = 16; o; o >>= 1) cs += __shfl_xor_sync(0xffffffff, cs, o);
            if (lane == 0) {
                ss4[h] = ss4[h] * fac + cs;
                sm4[h] = mnew;
                sf4[h] = fac;
            }
        }
        __syncthreads();
        float f = sf4[head];
        acc.x *= f; acc.y *= f; acc.z *= f; acc.w *= f;
        size_t hb = (size_t)head * 64 + f4;
        int j = 0;
        for (; j + 4 <= cnt; j += 4) {
            float a0 = wt[j][head], a1 = wt[j + 1][head];
            float a2 = wt[j + 2][head], a3 = wt[j + 3][head];
            float4 v0 = xp4[(size_t)ssrc[j] * 256 + hb];
            float4 v1 = xp4[(size_t)ssrc[j + 1] * 256 + hb];
            float4 v2 = xp4[(size_t)ssrc[j + 2] * 256 + hb];
            float4 v3 = xp4[(size_t)ssrc[j + 3] * 256 + hb];
            acc.x += a0 * v0.x + a1 * v1.x + a2 * v2.x + a3 * v3.x;
            acc.y += a0 * v0.y + a1 * v1.y + a2 * v2.y + a3 * v3.y;
            acc.z += a0 * v0.z + a1 * v1.z + a2 * v2.z + a3 * v3.z;
            acc.w += a0 * v0.w + a1 * v1.w + a2 * v2.w + a3 * v3.w;
        }
        for (; j < cnt; j++) {
            float a = wt[j][head];
            float4 v = xp4[(size_t)ssrc[j] * 256 + hb];
            acc.x += a * v.x;
            acc.y += a * v.y;
            acc.z += a * v.z;
            acc.w += a * v.w;
        }
        __syncthreads();   // before smem reuse next chunk
    }

    float inv = 0.25f / ss4[head];
    acc.x *= inv; acc.y *= inv; acc.z *= inv; acc.w *= inv;
    *(float4*)&sred[head * 256 + f4 * 4] = acc;
    __syncthreads();

    float h = sred[tid] + sred[256 + tid] + sred[512 + tid] + sred[768 + tid] + gat_b[tid];

    float v = h;
    for (int o = 16; o; o >>= 1) v += __shfl_xor_sync(0xffffffff, v, o);
    if (lane == 0) sw[wid] = v;
    __syncthreads();
    if (tid == 0) {
        float t = sw[0] + sw[1] + sw[2] + sw[3] + sw[4] + sw[5] + sw[6] + sw[7];
        sMu = t * (1.f / 256.f);
    }
    __syncthreads();
    float mu = sMu;
    float df = h - mu;
    v = df * df;
    for (int o = 16; o; o >>= 1) v += __shfl_xor_sync(0xffffffff, v, o);
    __syncthreads();
    if (lane == 0) sw[wid] = v;
    __syncthreads();
    if (tid == 0) {
        float t = sw[0] + sw[1] + sw[2] + sw[3] + sw[4] + sw[5] + sw[6] + sw[7];
        sVar = t * (1.f / 256.f);
    }
    __syncthreads();
    float y = ln_g[tid] * df * rsqrtf(sVar + 1e-5f) + ln_b[tid];
    size_t idx = (size_t)n * 256 + tid;
    float o = fmaxf(x[idx] + y, 0.f);
    xo[idx] = o;
    __nv_bfloat16 bh = __float2bfloat16(o);
    xh[idx] = bh;
    xl[idx] = __float2bfloat16(o - __bfloat162float(bh));
}

// ---------------- prediction heads epilogue ----------------
__global__ void k_headout(const float* __restrict__ w2, const float* __restrict__ b2,
                          float* __restrict__ out) {
    int n = blockIdx.x;
    int k = threadIdx.x >> 5, lane = threadIdx.x & 31;
    const float* hr = g_hmid + (size_t)n * 512 + k * 128;
    const float* w = w2 + k * 128;
    float s = 0.f;
    for (int i = lane; i < 128; i += 32) s += hr[i] * w[i];
    for (int o = 16; o; o >>= 1) s += __shfl_down_sync(0xffffffff, s, o);
    if (lane == 0) {
        float v = s + b2[k];
        if (k == 0 || k == 3) v = 1.f / (1.f + expf(-v));
        out[(size_t)k * NN + n] = v;
    }
}

// ---------------- launch ----------------
extern "C" void kernel_launch(void* const* d_in, const int* in_sizes, int n_in,
                              void* d_out, int out_size) {
    const float* node_features = (const float*)d_in[0];
    const float* edge_attr     = (const float*)d_in[1];
    const float* enc_w         = (const float*)d_in[2];
    const float* enc_b         = (const float*)d_in[3];
    const float* edge_enc_w    = (const float*)d_in[4];
    const float* edge_enc_b    = (const float*)d_in[5];
    const float* gat_w         = (const float*)d_in[6];
    const float* att_src       = (const float*)d_in[7];
    const float* att_dst       = (const float*)d_in[8];
    const float* att_edge      = (const float*)d_in[9];
    const float* lin_edge_w    = (const float*)d_in[10];
    const float* gat_b         = (const float*)d_in[11];
    const float* ln_g          = (const float*)d_in[12];
    const float* ln_b          = (const float*)d_in[13];
    const float* head_w1       = (const float*)d_in[14];
    const float* head_b1       = (const float*)d_in[15];
    const float* head_w2       = (const float*)d_in[16];
    const float* head_b2       = (const float*)d_in[17];
    const int*   src           = (const int*)d_in[18];
    const int*   dst           = src + EE;
    float* out = (float*)d_out;

    float *px, *px2, *pxp, *phmid;
    __nv_bfloat16 *pAh, *pAl, *pXh, *pXl, *pBh, *pBl;
    cudaGetSymbolAddress((void**)&px, g_x);
    cudaGetSymbolAddress((void**)&px2, g_x2);
    cudaGetSymbolAddress((void**)&pxp, g_xp);
    cudaGetSymbolAddress((void**)&phmid, g_hmid);
    cudaGetSymbolAddress((void**)&pAh, g_Ah);
    cudaGetSymbolAddress((void**)&pAl, g_Al);
    cudaGetSymbolAddress((void**)&pXh, g_Xh);
    cudaGetSymbolAddress((void**)&pXl, g_Xl);
    cudaGetSymbolAddress((void**)&pBh, g_Bh);
    cudaGetSymbolAddress((void**)&pBl, g_Bl);

    cudaFuncSetAttribute(k_mma, cudaFuncAttributeMaxDynamicSharedMemorySize, GEMM_SMEM);

    const int MT = (NN + 127) / 128;  // 157 M-tiles

    // ---- graph preprocessing (dst-CSR) + per-layer constants ----
    k_zero<<<(NN + 255) / 256, 256>>>();
    k_count<<<(EE + 255) / 256, 256>>>(dst);
    k_scan<<<1, 1024>>>();
    k_scatter<<<(EE + 255) / 256, 256>>>(src, dst);
    k_wmean<<<NL * EDIM, 256>>>(edge_enc_w);
    k_bmean<<<NL, 256>>>(edge_enc_b);
    k_cvec<<<NL * NHEADS, 256>>>(lin_edge_w, att_edge);
    k_ew3<<<(EE + 7) / 8, 256>>>(edge_attr);
    k_loopw3<<<(NN + 255) / 256, 256>>>();

    // ---- encoder: x = relu(nf @ enc_w + enc_b), emits fp32 + bf16 split ----
    k_cvtA<<<(NN * NDIM + 255) / 256, 256>>>(node_features, pAh, pAl, NN * NDIM);
    k_cvtBT<<<(NDIM * HD + 255) / 256, 256>>>(enc_w, pBh, pBl, NDIM, HD);
    k_mma<<<dim3(HD / 128, MT), 256, GEMM_SMEM>>>(pAh, pAl, pBh, pBl, px, pXh, pXl,
                                                  NN, HD, NDIM, enc_b, 1, nullptr, nullptr);

    // ---- 3 GAT layers ----
    for (int l = 0; l < NL; l++) {
        const float* A = (l & 1) ? px2 : px;
        float* XO      = (l == 2) ? out + 4 * NN : ((l & 1) ? px : px2);

        // xp = x @ gat_w[l], a_s/a_d fused into epilogue
        k_zeroAS<<<(NN * 4 + 255) / 256, 256>>>();
        k_cvtBT<<<(HD * 1024 + 255) / 256, 256>>>(gat_w + (size_t)l * 256 * 1024,
                                                  pBh, pBl, HD, 1024);
        k_mma<<<dim3(1024 / 128, MT), 256, GEMM_SMEM>>>(pXh, pXl, pBh, pBl, pxp,
                                                        nullptr, nullptr,
                                                        NN, 1024, HD, nullptr, 0,
                                                        att_src + l * 1024, att_dst + l * 1024);

        k_gather<<<NN, 256>>>(A, XO, pXh, pXl, l,
                              gat_b + l * 256, ln_g + l * 256, ln_b + l * 256);
    }
    // emb now lives directly in out[4*NN ..]; bf16 split in pXh/pXl

    // ---- combined prediction heads: hmid = relu(emb @ [W1_0|W1_1|W1_2|W1_3] + b1) ----
    k_cvtHW<<<(512 * 256 + 255) / 256, 256>>>(head_w1, pBh, pBl);
    k_mma<<<dim3(512 / 128, MT), 256, GEMM_SMEM>>>(pXh, pXl, pBh, pBl, phmid,
                                                   nullptr, nullptr,
                                                   NN, 512, HD, head_b1, 1, nullptr, nullptr);
    k_headout<<<NN, 128>>>(head_w2, head_b2, out);
}

// round 8
// speedup vs baseline: 2.4484x; 1.0999x over previous
#include <cuda_runtime.h>
#include <cuda_fp16.h>
#include <cstdint>
#include <math.h>

#define NN 20000
#define EE 200000
#define HD 256
#define NHEADS 4
#define NDIM 128
#define EDIM 64
#define NL 3

// ---------------- scratch (static device globals; no runtime allocation) ----------------
__device__ float g_x  [(size_t)NN * HD];
__device__ float g_x2 [(size_t)NN * HD];
__device__ float g_xp [(size_t)NN * NHEADS * HD];   // [N, 4, 256] = [N,1024]
__device__ float g_as [NN * NHEADS];
__device__ float g_ad [NN * NHEADS];
__device__ float g_ew [NL * EE];
__device__ float g_loopw[NL * NN];
__device__ int   g_counts[NN];
__device__ int   g_cursor[NN];
__device__ int   g_rowptr[NN + 1];
__device__ int   g_csrc[EE];
__device__ int   g_ceid[EE];
__device__ float g_hmid[(size_t)NN * 512];
__device__ float g_wmean[NL * EDIM];
__device__ float g_bmean[NL];
__device__ float g_cvec [NL * NHEADS];
// fp16 buffers for tensor-core GEMM (A single fp16; B split hi/lo fp16)
__device__ __half g_Ah[(size_t)NN * HD];   // encoder input (node features), fp16
__device__ __half g_Xh[(size_t)NN * HD];   // activation x, fp16 (produced by epilogues)
__device__ __half g_Bh[1024 * 256];
__device__ __half g_Bl[1024 * 256];

// ---------------- helpers ----------------
__device__ __forceinline__ float lrelu(float x) { return fmaxf(x, 0.2f * x); }

__device__ __forceinline__ void mma16816(float* c, const uint32_t* a, const uint32_t* b) {
    asm volatile(
        "mma.sync.aligned.m16n8k16.row.col.f32.f16.f16.f32 "
        "{%0,%1,%2,%3}, {%4,%5,%6,%7}, {%8,%9}, {%0,%1,%2,%3};"
        : "+f"(c[0]), "+f"(c[1]), "+f"(c[2]), "+f"(c[3])
        : "r"(a[0]), "r"(a[1]), "r"(a[2]), "r"(a[3]), "r"(b[0]), "r"(b[1]));
}
__device__ __forceinline__ void ldsm4(uint32_t addr, uint32_t* r) {
    asm volatile("ldmatrix.sync.aligned.m8n8.x4.shared.b16 {%0,%1,%2,%3}, [%4];"
                 : "=r"(r[0]), "=r"(r[1]), "=r"(r[2]), "=r"(r[3]) : "r"(addr));
}
__device__ __forceinline__ void cpa16z(uint32_t dst, const void* src, int sz) {
    asm volatile("cp.async.cg.shared.global [%0], [%1], 16, %2;"
                 :: "r"(dst), "l"(src), "r"(sz));
}

// ---------------- fp16x2 GEMM, double-buffered cp.async pipeline ----------------
// C[M,N] = A[M,K]@B[K,N] (+bias)(+relu); A fp16 [M,K] row-major; B split fp16 [N,K] row-major.
// Block 128x128, 8 warps (2Mx4N), warp 64x32, K-chunk 32, 2 stages, 2 MMAs per tile (a*bh + a*bl).
#define KCH 32
#define AST 40                       // smem row stride fp16 (80B: conflict-free ldmatrix)
#define STG (128 * AST)              // elems per buffer per stage
#define GEMM_SMEM (6 * STG * 2)      // 61440 bytes (A,Bh,Bl x 2 stages)
__global__ __launch_bounds__(256, 2) void k_mma(
    const __half* __restrict__ A,
    const __half* __restrict__ Bh, const __half* __restrict__ Bl,
    float* __restrict__ C, __half* __restrict__ Chi,
    int M, int N, int K, const float* __restrict__ bias, int doRelu,
    const float* __restrict__ attS, const float* __restrict__ attD) {
    extern __shared__ __half sm[];
    __shared__ float sAS[128], sAD[128];
    uint32_t base = (uint32_t)__cvta_generic_to_shared(sm);

    int tid = threadIdx.x, lane = tid & 31, wid = tid >> 5;
    int nb = blockIdx.x, mb = blockIdx.y;
    int warpM = wid >> 2, warpN = wid & 3;
    int gid = lane >> 2, qid = lane & 3;
    int NC = K / KCH;

    auto offA  = [&](int s) { return base + (uint32_t)(3 * s) * STG * 2; };
    auto offBh = [&](int s) { return base + (uint32_t)(3 * s + 1) * STG * 2; };
    auto offBl = [&](int s) { return base + (uint32_t)(3 * s + 2) * STG * 2; };

    auto load_chunk = [&](int kc, int s) {
        int k0 = kc * KCH;
#pragma unroll
        for (int i = tid; i < 512; i += 256) {
            int row = i >> 2, c = i & 3;
            uint32_t so = (uint32_t)(row * AST + c * 8) * 2;
            int gr = mb * 128 + row;
            int sz = (gr < M) ? 16 : 0;
            int grc = (gr < M) ? gr : (M - 1);
            cpa16z(offA(s) + so, A + (size_t)grc * K + k0 + c * 8, sz);
            int gn = nb * 128 + row;
            cpa16z(offBh(s) + so, Bh + (size_t)gn * K + k0 + c * 8, 16);
            cpa16z(offBl(s) + so, Bl + (size_t)gn * K + k0 + c * 8, 16);
        }
        asm volatile("cp.async.commit_group;");
    };

    float acc[4][4][4];
#pragma unroll
    for (int i = 0; i < 4; i++)
#pragma unroll
        for (int j = 0; j < 4; j++)
#pragma unroll
            for (int k = 0; k < 4; k++) acc[i][j][k] = 0.f;

    int aRow = (lane & 15), aCol = (lane >> 4) * 8;
    int bRow = (lane & 7) + ((lane >> 4) << 3), bCol = ((lane >> 3) & 1) * 8;

    load_chunk(0, 0);

    for (int kc = 0; kc < NC; kc++) {
        int s = kc & 1;
        if (kc + 1 < NC) {
            load_chunk(kc + 1, s ^ 1);
            asm volatile("cp.async.wait_group 1;" ::: "memory");
        } else {
            asm volatile("cp.async.wait_group 0;" ::: "memory");
        }
        __syncthreads();

#pragma unroll
        for (int ks = 0; ks < KCH; ks += 16) {
            uint32_t av[4][4], bh[2][4], bl[2][4];
#pragma unroll
            for (int mt = 0; mt < 4; mt++) {
                uint32_t o = (uint32_t)((warpM * 64 + mt * 16 + aRow) * AST + ks + aCol) * 2;
                ldsm4(offA(s) + o, av[mt]);
            }
#pragma unroll
            for (int np = 0; np < 2; np++) {
                uint32_t o = (uint32_t)((warpN * 32 + np * 16 + bRow) * AST + ks + bCol) * 2;
                ldsm4(offBh(s) + o, bh[np]);
                ldsm4(offBl(s) + o, bl[np]);
            }
#pragma unroll
            for (int mt = 0; mt < 4; mt++)
#pragma unroll
                for (int nt = 0; nt < 4; nt++) {
                    const uint32_t* bhp = &bh[nt >> 1][(nt & 1) * 2];
                    const uint32_t* blp = &bl[nt >> 1][(nt & 1) * 2];
                    mma16816(acc[mt][nt], av[mt], bhp);
                    mma16816(acc[mt][nt], av[mt], blp);
                }
        }
        __syncthreads();
    }

    // ---- fused attention dots: a_s[r,h] += sum_cn acc(r,cn)*attS[cn] (CTA covers 1 head) ----
    if (attS) {
        if (tid < 128) { sAS[tid] = 0.f; sAD[tid] = 0.f; }
        __syncthreads();
        float avS[8], avD[8];
#pragma unroll
        for (int nt = 0; nt < 4; nt++) {
            int cn = nb * 128 + warpN * 32 + nt * 8 + qid * 2;
            avS[nt * 2] = attS[cn];
            avS[nt * 2 + 1] = attS[cn + 1];
            avD[nt * 2] = attD[cn];
            avD[nt * 2 + 1] = attD[cn + 1];
        }
#pragma unroll
        for (int mt = 0; mt < 4; mt++)
#pragma unroll
            for (int half = 0; half < 2; half++) {
                float sp = 0.f, dp = 0.f;
#pragma unroll
                for (int nt = 0; nt < 4; nt++) {
                    float a0 = acc[mt][nt][half * 2], a1 = acc[mt][nt][half * 2 + 1];
                    sp += a0 * avS[nt * 2] + a1 * avS[nt * 2 + 1];
                    dp += a0 * avD[nt * 2] + a1 * avD[nt * 2 + 1];
                }
                sp += __shfl_xor_sync(0xffffffffu, sp, 1);
                sp += __shfl_xor_sync(0xffffffffu, sp, 2);
                dp += __shfl_xor_sync(0xffffffffu, dp, 1);
                dp += __shfl_xor_sync(0xffffffffu, dp, 2);
                if (qid == 0) {
                    int rl = warpM * 64 + mt * 16 + gid + half * 8;
                    atomicAdd(&sAS[rl], sp);
                    atomicAdd(&sAD[rl], dp);
                }
            }
        __syncthreads();
        if (tid < 128) {
            int r = mb * 128 + tid;
            if (r < M) {
                int h = nb >> 1;   // 128 cols/CTA, 256 cols/head
                atomicAdd(&g_as[r * 4 + h], sAS[tid]);
                atomicAdd(&g_ad[r * 4 + h], sAD[tid]);
            }
        }
    }

    // ---- C stores ----
#pragma unroll
    for (int mt = 0; mt < 4; mt++) {
        int r0 = mb * 128 + warpM * 64 + mt * 16 + gid;
#pragma unroll
        for (int nt = 0; nt < 4; nt++) {
            int cn = nb * 128 + warpN * 32 + nt * 8 + qid * 2;
            float b0 = bias ? bias[cn] : 0.f;
            float b1 = bias ? bias[cn + 1] : 0.f;
#pragma unroll
            for (int half = 0; half < 2; half++) {
                int r = r0 + half * 8;
                if (r < M) {
                    float v0 = acc[mt][nt][half * 2 + 0] + b0;
                    float v1 = acc[mt][nt][half * 2 + 1] + b1;
                    if (doRelu) { v0 = fmaxf(v0, 0.f); v1 = fmaxf(v1, 0.f); }
                    size_t o = (size_t)r * N + cn;
                    C[o] = v0;
                    C[o + 1] = v1;
                    if (Chi) {
                        Chi[o] = __float2half(v0);
                        Chi[o + 1] = __float2half(v1);
                    }
                }
            }
        }
    }
}

// ---------------- fp16 conversions ----------------
__global__ void k_cvtA(const float* __restrict__ in, __half* __restrict__ out, int n) {
    int i = blockIdx.x * 256 + threadIdx.x;
    if (i < n) out[i] = __float2half(in[i]);
}
// weights [K,N] fp32 -> [N,K] fp16 hi/lo (transpose; K-contiguous)
__global__ void k_cvtBT(const float* __restrict__ in, __half* __restrict__ hi,
                        __half* __restrict__ lo, int K, int N) {
    int i = blockIdx.x * 256 + threadIdx.x;
    if (i < K * N) {
        int kk = i / N, n = i % N;
        float v = in[i];
        __half h = __float2half(v);
        size_t o = (size_t)n * K + kk;
        hi[o] = h;
        lo[o] = __float2half(v - __half2float(h));
    }
}
// head_w1 [4][256][128] -> combined B [512][256] K-contiguous fp16 split
__global__ void k_cvtHW(const float* __restrict__ in, __half* __restrict__ hi,
                        __half* __restrict__ lo) {
    int i = blockIdx.x * 256 + threadIdx.x;   // over 512*256
    if (i < 512 * 256) {
        int n = i >> 8, kk = i & 255;
        float v = in[(n >> 7) * 32768 + kk * 128 + (n & 127)];
        __half h = __float2half(v);
        hi[i] = h;
        lo[i] = __float2half(v - __half2float(h));
    }
}
__global__ void k_zeroAS() {
    int i = blockIdx.x * 256 + threadIdx.x;
    if (i < NN * 4) { g_as[i] = 0.f; g_ad[i] = 0.f; }
}

// ---------------- preprocessing ----------------
__global__ void k_zero() {
    int i = blockIdx.x * 256 + threadIdx.x;
    if (i < NN) { g_counts[i] = 0; g_cursor[i] = 0; }
}
__global__ void k_count(const int* __restrict__ dst) {
    int e = blockIdx.x * 256 + threadIdx.x;
    if (e < EE) atomicAdd(&g_counts[dst[e]], 1);
}
__global__ void k_scan() {
    __shared__ int sh[1024];
    int tid = threadIdx.x;
    int carry = 0;
    for (int base = 0; base < NN; base += 1024) {
        int i = base + tid;
        int v = (i < NN) ? g_counts[i] : 0;
        sh[tid] = v;
        __syncthreads();
        for (int off = 1; off < 1024; off <<= 1) {
            int t = (tid >= off) ? sh[tid - off] : 0;
            __syncthreads();
            sh[tid] += t;
            __syncthreads();
        }
        if (i < NN) g_rowptr[i + 1] = carry + sh[tid];
        carry += sh[1023];
        __syncthreads();
    }
    if (tid == 0) g_rowptr[0] = 0;
}
__global__ void k_scatter(const int* __restrict__ src, const int* __restrict__ dst) {
    int e = blockIdx.x * 256 + threadIdx.x;
    if (e < EE) {
        int d = dst[e];
        int pos = g_rowptr[d] + atomicAdd(&g_cursor[d], 1);
        g_csrc[pos] = src[e];
        g_ceid[pos] = e;
    }
}
__global__ void k_wmean(const float* __restrict__ W) {
    __shared__ float red[256];
    int ld = blockIdx.x;
    red[threadIdx.x] = W[(size_t)ld * 256 + threadIdx.x];
    __syncthreads();
    for (int s = 128; s; s >>= 1) {
        if (threadIdx.x < s) red[threadIdx.x] += red[threadIdx.x + s];
        __syncthreads();
    }
    if (threadIdx.x == 0) g_wmean[ld] = red[0] * (1.f / 256.f);
}
__global__ void k_bmean(const float* __restrict__ b) {
    __shared__ float red[256];
    int l = blockIdx.x;
    red[threadIdx.x] = b[l * 256 + threadIdx.x];
    __syncthreads();
    for (int s = 128; s; s >>= 1) {
        if (threadIdx.x < s) red[threadIdx.x] += red[threadIdx.x + s];
        __syncthreads();
    }
    if (threadIdx.x == 0) g_bmean[l] = red[0] * (1.f / 256.f);
}
__global__ void k_cvec(const float* __restrict__ lew, const float* __restrict__ ae) {
    __shared__ float red[256];
    int lh = blockIdx.x;
    size_t off = (size_t)lh * 256 + threadIdx.x;
    red[threadIdx.x] = lew[off] * ae[off];
    __syncthreads();
    for (int s = 128; s; s >>= 1) {
        if (threadIdx.x < s) red[threadIdx.x] += red[threadIdx.x + s];
        __syncthreads();
    }
    if (threadIdx.x == 0) g_cvec[lh] = red[0];
}

// ew for ALL layers in one pass over edge_attr (warp per edge)
__global__ void k_ew3(const float* __restrict__ ea) {
    int warp = threadIdx.x >> 5, lane = threadIdx.x & 31;
    int e = blockIdx.x * 8 + warp;
    if (e >= EE) return;
    const float* row = ea + (size_t)e * EDIM;
    float v0 = row[lane], v1 = row[lane + 32];
    float s0 = v0 * g_wmean[lane] + v1 * g_wmean[lane + 32];
    float s1 = v0 * g_wmean[64 + lane] + v1 * g_wmean[64 + lane + 32];
    float s2 = v0 * g_wmean[128 + lane] + v1 * g_wmean[128 + lane + 32];
    for (int o = 16; o; o >>= 1) {
        s0 += __shfl_down_sync(0xffffffff, s0, o);
        s1 += __shfl_down_sync(0xffffffff, s1, o);
        s2 += __shfl_down_sync(0xffffffff, s2, o);
    }
    if (lane == 0) {
        g_ew[e] = s0 + g_bmean[0];
        g_ew[EE + e] = s1 + g_bmean[1];
        g_ew[2 * EE + e] = s2 + g_bmean[2];
    }
}

__global__ void k_loopw3() {
    int n = blockIdx.x * 256 + threadIdx.x;
    if (n < NN) {
        int b = g_rowptr[n], e = g_rowptr[n + 1];
        float s0 = 0.f, s1 = 0.f, s2 = 0.f;
        for (int p = b; p < e; p++) {
            int id = g_ceid[p];
            s0 += g_ew[id];
            s1 += g_ew[EE + id];
            s2 += g_ew[2 * EE + id];
        }
        float inv = 1.f / fmaxf((float)(e - b), 1.f);
        g_loopw[n] = s0 * inv;
        g_loopw[NN + n] = s1 * inv;
        g_loopw[2 * NN + n] = s2 * inv;
    }
}

// ---------------- fused GAT: online softmax + gather + bias + LN + residual + fp16 out ----------------
#define GCH 128
__global__ __launch_bounds__(256) void k_gather(const float* __restrict__ x,
                                                float* __restrict__ xo,
                                                __half* __restrict__ xh,
                                                int l,
                                                const float* __restrict__ gat_b,
                                                const float* __restrict__ ln_g,
                                                const float* __restrict__ ln_b) {
    int n = blockIdx.x, tid = threadIdx.x;
    int lane = tid & 31, wid = tid >> 5;
    int head = tid >> 6, f4 = tid & 63;
    __shared__ int ssrc[GCH];
    __shared__ float slog[GCH][4];
    __shared__ float wt[GCH][4];
    __shared__ float sm4[4], ss4[4], sf4[4];
    __shared__ float sred[1024];
    __shared__ float sw[8];
    __shared__ float sMu, sVar;

    int beg = g_rowptr[n];
    int deg = g_rowptr[n + 1] - beg;

    float4 adv = *(const float4*)&g_ad[n * 4];
    float4 cv = *(const float4*)&g_cvec[l * 4];
    float lw = g_loopw[l * NN + n];
    if (tid < 4) {
        float sl = lrelu(g_as[n * 4 + tid] + g_ad[n * 4 + tid] + lw * g_cvec[l * 4 + tid]);
        sm4[tid] = sl;
        ss4[tid] = 1.f;
    }
    __syncthreads();

    const float4* xp4 = (const float4*)g_xp;
    float4 acc = xp4[(size_t)n * 256 + head * 64 + f4];  // self, weight 1 at current max

    for (int ch = 0; ch < deg; ch += GCH) {
        int cnt = min(GCH, deg - ch);
        if (tid < cnt) {
            int p = beg + ch + tid;
            int s0 = g_csrc[p];
            float w = g_ew[l * EE + g_ceid[p]];
            ssrc[tid] = s0;
            float4 as4 = *(const float4*)&g_as[s0 * 4];
            slog[tid][0] = lrelu(as4.x + adv.x + w * cv.x);
            slog[tid][1] = lrelu(as4.y + adv.y + w * cv.y);
            slog[tid][2] = lrelu(as4.z + adv.z + w * cv.z);
            slog[tid][3] = lrelu(as4.w + adv.w + w * cv.w);
        }
        __syncthreads();
        if (wid < 4) {
            int h = wid;
            float cm = -1e30f;
            for (int j = lane; j < cnt; j += 32) cm = fmaxf(cm, slog[j][h]);
            for (int o = 16; o; o >>= 1) cm = fmaxf(cm, __shfl_xor_sync(0xffffffff, cm, o));
            float mold = sm4[h];
            float mnew = fmaxf(mold, cm);
            float fac = expf(mold - mnew);
            float cs = 0.f;
            for (int j = lane; j < cnt; j += 32) {
                float p = expf(slog[j][h] - mnew);
                wt[j][h] = p;
                cs += p;
            }
            for (int o = 16; o; o >>= 1) cs += __shfl_xor_sync(0xffffffff, cs, o);
            if (lane == 0) {
                ss4[h] = ss4[h] * fac + cs;
                sm4[h] = mnew;
                sf4[h] = fac;
            }
        }
        __syncthreads();
        float f = sf4[head];
        acc.x *= f; acc.y *= f; acc.z *= f; acc.w *= f;
        size_t hb = (size_t)head * 64 + f4;
        int j = 0;
        for (; j + 4 <= cnt; j += 4) {
            float a0 = wt[j][head], a1 = wt[j + 1][head];
            float a2 = wt[j + 2][head], a3 = wt[j + 3][head];
            float4 v0 = xp4[(size_t)ssrc[j] * 256 + hb];
            float4 v1 = xp4[(size_t)ssrc[j + 1] * 256 + hb];
            float4 v2 = xp4[(size_t)ssrc[j + 2] * 256 + hb];
            float4 v3 = xp4[(size_t)ssrc[j + 3] * 256 + hb];
            acc.x += a0 * v0.x + a1 * v1.x + a2 * v2.x + a3 * v3.x;
            acc.y += a0 * v0.y + a1 * v1.y + a2 * v2.y + a3 * v3.y;
            acc.z += a0 * v0.z + a1 * v1.z + a2 * v2.z + a3 * v3.z;
            acc.w += a0 * v0.w + a1 * v1.w + a2 * v2.w + a3 * v3.w;
        }
        for (; j < cnt; j++) {
            float a = wt[j][head];
            float4 v = xp4[(size_t)ssrc[j] * 256 + hb];
            acc.x += a * v.x;
            acc.y += a * v.y;
            acc.z += a * v.z;
            acc.w += a * v.w;
        }
        __syncthreads();   // before smem reuse next chunk
    }

    float inv = 0.25f / ss4[head];
    acc.x *= inv; acc.y *= inv; acc.z *= inv; acc.w *= inv;
    *(float4*)&sred[head * 256 + f4 * 4] = acc;
    __syncthreads();

    float h = sred[tid] + sred[256 + tid] + sred[512 + tid] + sred[768 + tid] + gat_b[tid];

    float v = h;
    for (int o = 16; o; o >>= 1) v += __shfl_xor_sync(0xffffffff, v, o);
    if (lane == 0) sw[wid] = v;
    __syncthreads();
    if (tid == 0) {
        float t = sw[0] + sw[1] + sw[2] + sw[3] + sw[4] + sw[5] + sw[6] + sw[7];
        sMu = t * (1.f / 256.f);
    }
    __syncthreads();
    float mu = sMu;
    float df = h - mu;
    v = df * df;
    for (int o = 16; o; o >>= 1) v += __shfl_xor_sync(0xffffffff, v, o);
    __syncthreads();
    if (lane == 0) sw[wid] = v;
    __syncthreads();
    if (tid == 0) {
        float t = sw[0] + sw[1] + sw[2] + sw[3] + sw[4] + sw[5] + sw[6] + sw[7];
        sVar = t * (1.f / 256.f);
    }
    __syncthreads();
    float y = ln_g[tid] * df * rsqrtf(sVar + 1e-5f) + ln_b[tid];
    size_t idx = (size_t)n * 256 + tid;
    float o = fmaxf(x[idx] + y, 0.f);
    xo[idx] = o;
    xh[idx] = __float2half(o);
}

// ---------------- prediction heads epilogue ----------------
__global__ void k_headout(const float* __restrict__ w2, const float* __restrict__ b2,
                          float* __restrict__ out) {
    int n = blockIdx.x;
    int k = threadIdx.x >> 5, lane = threadIdx.x & 31;
    const float* hr = g_hmid + (size_t)n * 512 + k * 128;
    const float* w = w2 + k * 128;
    float s = 0.f;
    for (int i = lane; i < 128; i += 32) s += hr[i] * w[i];
    for (int o = 16; o; o >>= 1) s += __shfl_down_sync(0xffffffff, s, o);
    if (lane == 0) {
        float v = s + b2[k];
        if (k == 0 || k == 3) v = 1.f / (1.f + expf(-v));
        out[(size_t)k * NN + n] = v;
    }
}

// ---------------- launch ----------------
extern "C" void kernel_launch(void* const* d_in, const int* in_sizes, int n_in,
                              void* d_out, int out_size) {
    const float* node_features = (const float*)d_in[0];
    const float* edge_attr     = (const float*)d_in[1];
    const float* enc_w         = (const float*)d_in[2];
    const float* enc_b         = (const float*)d_in[3];
    const float* edge_enc_w    = (const float*)d_in[4];
    const float* edge_enc_b    = (const float*)d_in[5];
    const float* gat_w         = (const float*)d_in[6];
    const float* att_src       = (const float*)d_in[7];
    const float* att_dst       = (const float*)d_in[8];
    const float* att_edge      = (const float*)d_in[9];
    const float* lin_edge_w    = (const float*)d_in[10];
    const float* gat_b         = (const float*)d_in[11];
    const float* ln_g          = (const float*)d_in[12];
    const float* ln_b          = (const float*)d_in[13];
    const float* head_w1       = (const float*)d_in[14];
    const float* head_b1       = (const float*)d_in[15];
    const float* head_w2       = (const float*)d_in[16];
    const float* head_b2       = (const float*)d_in[17];
    const int*   src           = (const int*)d_in[18];
    const int*   dst           = src + EE;
    float* out = (float*)d_out;

    float *px, *px2, *pxp, *phmid;
    __half *pAh, *pXh, *pBh, *pBl;
    cudaGetSymbolAddress((void**)&px, g_x);
    cudaGetSymbolAddress((void**)&px2, g_x2);
    cudaGetSymbolAddress((void**)&pxp, g_xp);
    cudaGetSymbolAddress((void**)&phmid, g_hmid);
    cudaGetSymbolAddress((void**)&pAh, g_Ah);
    cudaGetSymbolAddress((void**)&pXh, g_Xh);
    cudaGetSymbolAddress((void**)&pBh, g_Bh);
    cudaGetSymbolAddress((void**)&pBl, g_Bl);

    cudaFuncSetAttribute(k_mma, cudaFuncAttributeMaxDynamicSharedMemorySize, GEMM_SMEM);

    const int MT = (NN + 127) / 128;  // 157 M-tiles

    // ---- graph preprocessing (dst-CSR) + per-layer constants ----
    k_zero<<<(NN + 255) / 256, 256>>>();
    k_count<<<(EE + 255) / 256, 256>>>(dst);
    k_scan<<<1, 1024>>>();
    k_scatter<<<(EE + 255) / 256, 256>>>(src, dst);
    k_wmean<<<NL * EDIM, 256>>>(edge_enc_w);
    k_bmean<<<NL, 256>>>(edge_enc_b);
    k_cvec<<<NL * NHEADS, 256>>>(lin_edge_w, att_edge);
    k_ew3<<<(EE + 7) / 8, 256>>>(edge_attr);
    k_loopw3<<<(NN + 255) / 256, 256>>>();

    // ---- encoder: x = relu(nf @ enc_w + enc_b), emits fp32 + fp16 ----
    k_cvtA<<<(NN * NDIM + 255) / 256, 256>>>(node_features, pAh, NN * NDIM);
    k_cvtBT<<<(NDIM * HD + 255) / 256, 256>>>(enc_w, pBh, pBl, NDIM, HD);
    k_mma<<<dim3(HD / 128, MT), 256, GEMM_SMEM>>>(pAh, pBh, pBl, px, pXh,
                                                  NN, HD, NDIM, enc_b, 1, nullptr, nullptr);

    // ---- 3 GAT layers ----
    for (int l = 0; l < NL; l++) {
        const float* A = (l & 1) ? px2 : px;
        float* XO      = (l == 2) ? out + 4 * NN : ((l & 1) ? px : px2);

        // xp = x @ gat_w[l], a_s/a_d fused into epilogue
        k_zeroAS<<<(NN * 4 + 255) / 256, 256>>>();
        k_cvtBT<<<(HD * 1024 + 255) / 256, 256>>>(gat_w + (size_t)l * 256 * 1024,
                                                  pBh, pBl, HD, 1024);
        k_mma<<<dim3(1024 / 128, MT), 256, GEMM_SMEM>>>(pXh, pBh, pBl, pxp, nullptr,
                                                        NN, 1024, HD, nullptr, 0,
                                                        att_src + l * 1024, att_dst + l * 1024);

        k_gather<<<NN, 256>>>(A, XO, pXh, l,
                              gat_b + l * 256, ln_g + l * 256, ln_b + l * 256);
    }
    // emb now lives directly in out[4*NN ..]; fp16 copy in pXh

    // ---- combined prediction heads: hmid = relu(emb @ [W1_0|W1_1|W1_2|W1_3] + b1) ----
    k_cvtHW<<<(512 * 256 + 255) / 256, 256>>>(head_w1, pBh, pBl);
    k_mma<<<dim3(512 / 128, MT), 256, GEMM_SMEM>>>(pXh, pBh, pBl, phmid, nullptr,
                                                   NN, 512, HD, head_b1, 1, nullptr, nullptr);
    k_headout<<<NN, 128>>>(head_w2, head_b2, out);
}

// round 9
// speedup vs baseline: 2.5520x; 1.0423x over previous
#include <cuda_runtime.h>
#include <cuda_fp16.h>
#include <cstdint>
#include <math.h>

#define NN 20000
#define EE 200000
#define HD 256
#define NHEADS 4
#define NDIM 128
#define EDIM 64
#define NL 3

// ---------------- scratch (static device globals; no runtime allocation) ----------------
__device__ float g_x  [(size_t)NN * HD];
__device__ float g_x2 [(size_t)NN * HD];
__device__ __half g_xph[(size_t)NN * NHEADS * HD];  // xp in fp16 [N,1024]
__device__ float g_as [NN * NHEADS];
__device__ float g_ad [NN * NHEADS];
__device__ float g_ew [NL * EE];
__device__ float g_loopw[NL * NN];
__device__ int   g_counts[NN];
__device__ int   g_cursor[NN];
__device__ int   g_rowptr[NN + 1];
__device__ int   g_csrc[EE];
__device__ int   g_ceid[EE];
__device__ float g_hmid[(size_t)NN * 512];
__device__ float g_wmean[NL * EDIM];
__device__ float g_bmean[NL];
__device__ float g_cvec [NL * NHEADS];
// fp16 hi/lo split buffers (A = activations, B = weights)
__device__ __half g_Ah[(size_t)NN * HD];
__device__ __half g_Al[(size_t)NN * HD];
__device__ __half g_Xh[(size_t)NN * HD];
__device__ __half g_Xl[(size_t)NN * HD];
__device__ __half g_Bh[1024 * 256];
__device__ __half g_Bl[1024 * 256];

// ---------------- helpers ----------------
__device__ __forceinline__ float lrelu(float x) { return fmaxf(x, 0.2f * x); }

__device__ __forceinline__ void mma16816(float* c, const uint32_t* a, const uint32_t* b) {
    asm volatile(
        "mma.sync.aligned.m16n8k16.row.col.f32.f16.f16.f32 "
        "{%0,%1,%2,%3}, {%4,%5,%6,%7}, {%8,%9}, {%0,%1,%2,%3};"
        : "+f"(c[0]), "+f"(c[1]), "+f"(c[2]), "+f"(c[3])
        : "r"(a[0]), "r"(a[1]), "r"(a[2]), "r"(a[3]), "r"(b[0]), "r"(b[1]));
}
__device__ __forceinline__ void ldsm4(uint32_t addr, uint32_t* r) {
    asm volatile("ldmatrix.sync.aligned.m8n8.x4.shared.b16 {%0,%1,%2,%3}, [%4];"
                 : "=r"(r[0]), "=r"(r[1]), "=r"(r[2]), "=r"(r[3]) : "r"(addr));
}
__device__ __forceinline__ void cpa16z(uint32_t dst, const void* src, int sz) {
    asm volatile("cp.async.cg.shared.global [%0], [%1], 16, %2;"
                 :: "r"(dst), "l"(src), "r"(sz));
}
__device__ __forceinline__ float4 h4tof4(uint2 u) {
    __half2 a = *(__half2*)&u.x, b = *(__half2*)&u.y;
    float2 fa = __half22float2(a), fb = __half22float2(b);
    return make_float4(fa.x, fa.y, fb.x, fb.y);
}

// ---------------- fp16x3 GEMM (A,B both hi/lo split), double-buffered cp.async ----------------
// C = A@B; error ~2^-21 (dropped al*bl). Block 128x128, 8 warps, warp 64x32, K-chunk 32.
#define KCH 32
#define AST 40                       // smem row stride fp16 (80B: conflict-free ldmatrix)
#define STG (128 * AST)
#define GEMM_SMEM (8 * STG * 2)      // 81920 bytes (Ah,Al,Bh,Bl x 2 stages)
__global__ __launch_bounds__(256, 2) void k_mma(
    const __half* __restrict__ Ah, const __half* __restrict__ Al,
    const __half* __restrict__ Bh, const __half* __restrict__ Bl,
    float* __restrict__ C, __half* __restrict__ Cxp,
    __half* __restrict__ Chi, __half* __restrict__ Clo,
    int M, int N, int K, const float* __restrict__ bias, int doRelu,
    const float* __restrict__ attS, const float* __restrict__ attD) {
    extern __shared__ __half sm[];
    __shared__ float sAS[128], sAD[128];
    uint32_t base = (uint32_t)__cvta_generic_to_shared(sm);

    int tid = threadIdx.x, lane = tid & 31, wid = tid >> 5;
    int nb = blockIdx.x, mb = blockIdx.y;
    int warpM = wid >> 2, warpN = wid & 3;
    int gid = lane >> 2, qid = lane & 3;
    int NC = K / KCH;

    auto offAh = [&](int s) { return base + (uint32_t)(4 * s) * STG * 2; };
    auto offAl = [&](int s) { return base + (uint32_t)(4 * s + 1) * STG * 2; };
    auto offBh = [&](int s) { return base + (uint32_t)(4 * s + 2) * STG * 2; };
    auto offBl = [&](int s) { return base + (uint32_t)(4 * s + 3) * STG * 2; };

    auto load_chunk = [&](int kc, int s) {
        int k0 = kc * KCH;
#pragma unroll
        for (int i = tid; i < 512; i += 256) {
            int row = i >> 2, c = i & 3;
            uint32_t so = (uint32_t)(row * AST + c * 8) * 2;
            int gr = mb * 128 + row;
            int sz = (gr < M) ? 16 : 0;
            int grc = (gr < M) ? gr : (M - 1);
            cpa16z(offAh(s) + so, Ah + (size_t)grc * K + k0 + c * 8, sz);
            cpa16z(offAl(s) + so, Al + (size_t)grc * K + k0 + c * 8, sz);
            int gn = nb * 128 + row;
            cpa16z(offBh(s) + so, Bh + (size_t)gn * K + k0 + c * 8, 16);
            cpa16z(offBl(s) + so, Bl + (size_t)gn * K + k0 + c * 8, 16);
        }
        asm volatile("cp.async.commit_group;");
    };

    float acc[4][4][4];
#pragma unroll
    for (int i = 0; i < 4; i++)
#pragma unroll
        for (int j = 0; j < 4; j++)
#pragma unroll
            for (int k = 0; k < 4; k++) acc[i][j][k] = 0.f;

    int aRow = (lane & 15), aCol = (lane >> 4) * 8;
    int bRow = (lane & 7) + ((lane >> 4) << 3), bCol = ((lane >> 3) & 1) * 8;

    load_chunk(0, 0);

    for (int kc = 0; kc < NC; kc++) {
        int s = kc & 1;
        if (kc + 1 < NC) {
            load_chunk(kc + 1, s ^ 1);
            asm volatile("cp.async.wait_group 1;" ::: "memory");
        } else {
            asm volatile("cp.async.wait_group 0;" ::: "memory");
        }
        __syncthreads();

#pragma unroll
        for (int ks = 0; ks < KCH; ks += 16) {
            uint32_t ah[4][4], al[4][4], bh[2][4], bl[2][4];
#pragma unroll
            for (int mt = 0; mt < 4; mt++) {
                uint32_t o = (uint32_t)((warpM * 64 + mt * 16 + aRow) * AST + ks + aCol) * 2;
                ldsm4(offAh(s) + o, ah[mt]);
                ldsm4(offAl(s) + o, al[mt]);
            }
#pragma unroll
            for (int np = 0; np < 2; np++) {
                uint32_t o = (uint32_t)((warpN * 32 + np * 16 + bRow) * AST + ks + bCol) * 2;
                ldsm4(offBh(s) + o, bh[np]);
                ldsm4(offBl(s) + o, bl[np]);
            }
#pragma unroll
            for (int mt = 0; mt < 4; mt++)
#pragma unroll
                for (int nt = 0; nt < 4; nt++) {
                    const uint32_t* bhp = &bh[nt >> 1][(nt & 1) * 2];
                    const uint32_t* blp = &bl[nt >> 1][(nt & 1) * 2];
                    mma16816(acc[mt][nt], ah[mt], bhp);
                    mma16816(acc[mt][nt], al[mt], bhp);
                    mma16816(acc[mt][nt], ah[mt], blp);
                }
        }
        __syncthreads();
    }

    // ---- fused attention dots from exact fp32 accumulators (CTA covers 1 head) ----
    if (attS) {
        if (tid < 128) { sAS[tid] = 0.f; sAD[tid] = 0.f; }
        __syncthreads();
        float avS[8], avD[8];
#pragma unroll
        for (int nt = 0; nt < 4; nt++) {
            int cn = nb * 128 + warpN * 32 + nt * 8 + qid * 2;
            avS[nt * 2] = attS[cn];
            avS[nt * 2 + 1] = attS[cn + 1];
            avD[nt * 2] = attD[cn];
            avD[nt * 2 + 1] = attD[cn + 1];
        }
#pragma unroll
        for (int mt = 0; mt < 4; mt++)
#pragma unroll
            for (int half = 0; half < 2; half++) {
                float sp = 0.f, dp = 0.f;
#pragma unroll
                for (int nt = 0; nt < 4; nt++) {
                    float a0 = acc[mt][nt][half * 2], a1 = acc[mt][nt][half * 2 + 1];
                    sp += a0 * avS[nt * 2] + a1 * avS[nt * 2 + 1];
                    dp += a0 * avD[nt * 2] + a1 * avD[nt * 2 + 1];
                }
                sp += __shfl_xor_sync(0xffffffffu, sp, 1);
                sp += __shfl_xor_sync(0xffffffffu, sp, 2);
                dp += __shfl_xor_sync(0xffffffffu, dp, 1);
                dp += __shfl_xor_sync(0xffffffffu, dp, 2);
                if (qid == 0) {
                    int rl = warpM * 64 + mt * 16 + gid + half * 8;
                    atomicAdd(&sAS[rl], sp);
                    atomicAdd(&sAD[rl], dp);
                }
            }
        __syncthreads();
        if (tid < 128) {
            int r = mb * 128 + tid;
            if (r < M) {
                int h = nb >> 1;   // 128 cols/CTA, 256 cols/head
                atomicAdd(&g_as[r * 4 + h], sAS[tid]);
                atomicAdd(&g_ad[r * 4 + h], sAD[tid]);
            }
        }
    }

    // ---- stores: C fp32 (optional), Cxp fp16 (optional), Chi/Clo hi-lo split (optional) ----
#pragma unroll
    for (int mt = 0; mt < 4; mt++) {
        int r0 = mb * 128 + warpM * 64 + mt * 16 + gid;
#pragma unroll
        for (int nt = 0; nt < 4; nt++) {
            int cn = nb * 128 + warpN * 32 + nt * 8 + qid * 2;
            float b0 = bias ? bias[cn] : 0.f;
            float b1 = bias ? bias[cn + 1] : 0.f;
#pragma unroll
            for (int half = 0; half < 2; half++) {
                int r = r0 + half * 8;
                if (r < M) {
                    float v0 = acc[mt][nt][half * 2 + 0] + b0;
                    float v1 = acc[mt][nt][half * 2 + 1] + b1;
                    if (doRelu) { v0 = fmaxf(v0, 0.f); v1 = fmaxf(v1, 0.f); }
                    size_t o = (size_t)r * N + cn;
                    if (C) {
                        C[o] = v0;
                        C[o + 1] = v1;
                    }
                    if (Cxp) {
                        *(__half2*)&Cxp[o] = __floats2half2_rn(v0, v1);
                    }
                    if (Chi) {
                        __half h0 = __float2half(v0);
                        __half h1 = __float2half(v1);
                        __half l0 = __float2half(v0 - __half2float(h0));
                        __half l1 = __float2half(v1 - __half2float(h1));
                        __half2 hh, ll;
                        hh.x = h0; hh.y = h1;
                        ll.x = l0; ll.y = l1;
                        *(__half2*)&Chi[o] = hh;
                        *(__half2*)&Clo[o] = ll;
                    }
                }
            }
        }
    }
}

// ---------------- fp16 hi/lo conversions ----------------
__global__ void k_cvtA(const float* __restrict__ in, __half* __restrict__ hi,
                       __half* __restrict__ lo, int n) {
    int i = blockIdx.x * 256 + threadIdx.x;
    if (i < n) {
        float v = in[i];
        __half h = __float2half(v);
        hi[i] = h;
        lo[i] = __float2half(v - __half2float(h));
    }
}
// weights [K,N] fp32 -> [N,K] fp16 hi/lo (transpose; K-contiguous)
__global__ void k_cvtBT(const float* __restrict__ in, __half* __restrict__ hi,
                        __half* __restrict__ lo, int K, int N) {
    int i = blockIdx.x * 256 + threadIdx.x;
    if (i < K * N) {
        int kk = i / N, n = i % N;
        float v = in[i];
        __half h = __float2half(v);
        size_t o = (size_t)n * K + kk;
        hi[o] = h;
        lo[o] = __float2half(v - __half2float(h));
    }
}
// head_w1 [4][256][128] -> combined B [512][256] K-contiguous fp16 split
__global__ void k_cvtHW(const float* __restrict__ in, __half* __restrict__ hi,
                        __half* __restrict__ lo) {
    int i = blockIdx.x * 256 + threadIdx.x;   // over 512*256
    if (i < 512 * 256) {
        int n = i >> 8, kk = i & 255;
        float v = in[(n >> 7) * 32768 + kk * 128 + (n & 127)];
        __half h = __float2half(v);
        hi[i] = h;
        lo[i] = __float2half(v - __half2float(h));
    }
}
__global__ void k_zeroAS() {
    int i = blockIdx.x * 256 + threadIdx.x;
    if (i < NN * 4) { g_as[i] = 0.f; g_ad[i] = 0.f; }
}

// ---------------- preprocessing ----------------
__global__ void k_zero() {
    int i = blockIdx.x * 256 + threadIdx.x;
    if (i < NN) { g_counts[i] = 0; g_cursor[i] = 0; }
}
__global__ void k_count(const int* __restrict__ dst) {
    int e = blockIdx.x * 256 + threadIdx.x;
    if (e < EE) atomicAdd(&g_counts[dst[e]], 1);
}
__global__ void k_scan() {
    __shared__ int sh[1024];
    int tid = threadIdx.x;
    int carry = 0;
    for (int base = 0; base < NN; base += 1024) {
        int i = base + tid;
        int v = (i < NN) ? g_counts[i] : 0;
        sh[tid] = v;
        __syncthreads();
        for (int off = 1; off < 1024; off <<= 1) {
            int t = (tid >= off) ? sh[tid - off] : 0;
            __syncthreads();
            sh[tid] += t;
            __syncthreads();
        }
        if (i < NN) g_rowptr[i + 1] = carry + sh[tid];
        carry += sh[1023];
        __syncthreads();
    }
    if (tid == 0) g_rowptr[0] = 0;
}
__global__ void k_scatter(const int* __restrict__ src, const int* __restrict__ dst) {
    int e = blockIdx.x * 256 + threadIdx.x;
    if (e < EE) {
        int d = dst[e];
        int pos = g_rowptr[d] + atomicAdd(&g_cursor[d], 1);
        g_csrc[pos] = src[e];
        g_ceid[pos] = e;
    }
}
__global__ void k_wmean(const float* __restrict__ W) {
    __shared__ float red[256];
    int ld = blockIdx.x;
    red[threadIdx.x] = W[(size_t)ld * 256 + threadIdx.x];
    __syncthreads();
    for (int s = 128; s; s >>= 1) {
        if (threadIdx.x < s) red[threadIdx.x] += red[threadIdx.x + s];
        __syncthreads();
    }
    if (threadIdx.x == 0) g_wmean[ld] = red[0] * (1.f / 256.f);
}
__global__ void k_bmean(const float* __restrict__ b) {
    __shared__ float red[256];
    int l = blockIdx.x;
    red[threadIdx.x] = b[l * 256 + threadIdx.x];
    __syncthreads();
    for (int s = 128; s; s >>= 1) {
        if (threadIdx.x < s) red[threadIdx.x] += red[threadIdx.x + s];
        __syncthreads();
    }
    if (threadIdx.x == 0) g_bmean[l] = red[0] * (1.f / 256.f);
}
__global__ void k_cvec(const float* __restrict__ lew, const float* __restrict__ ae) {
    __shared__ float red[256];
    int lh = blockIdx.x;
    size_t off = (size_t)lh * 256 + threadIdx.x;
    red[threadIdx.x] = lew[off] * ae[off];
    __syncthreads();
    for (int s = 128; s; s >>= 1) {
        if (threadIdx.x < s) red[threadIdx.x] += red[threadIdx.x + s];
        __syncthreads();
    }
    if (threadIdx.x == 0) g_cvec[lh] = red[0];
}

// ew for ALL layers in one pass over edge_attr (warp per edge)
__global__ void k_ew3(const float* __restrict__ ea) {
    int warp = threadIdx.x >> 5, lane = threadIdx.x & 31;
    int e = blockIdx.x * 8 + warp;
    if (e >= EE) return;
    const float* row = ea + (size_t)e * EDIM;
    float v0 = row[lane], v1 = row[lane + 32];
    float s0 = v0 * g_wmean[lane] + v1 * g_wmean[lane + 32];
    float s1 = v0 * g_wmean[64 + lane] + v1 * g_wmean[64 + lane + 32];
    float s2 = v0 * g_wmean[128 + lane] + v1 * g_wmean[128 + lane + 32];
    for (int o = 16; o; o >>= 1) {
        s0 += __shfl_down_sync(0xffffffff, s0, o);
        s1 += __shfl_down_sync(0xffffffff, s1, o);
        s2 += __shfl_down_sync(0xffffffff, s2, o);
    }
    if (lane == 0) {
        g_ew[e] = s0 + g_bmean[0];
        g_ew[EE + e] = s1 + g_bmean[1];
        g_ew[2 * EE + e] = s2 + g_bmean[2];
    }
}

__global__ void k_loopw3() {
    int n = blockIdx.x * 256 + threadIdx.x;
    if (n < NN) {
        int b = g_rowptr[n], e = g_rowptr[n + 1];
        float s0 = 0.f, s1 = 0.f, s2 = 0.f;
        for (int p = b; p < e; p++) {
            int id = g_ceid[p];
            s0 += g_ew[id];
            s1 += g_ew[EE + id];
            s2 += g_ew[2 * EE + id];
        }
        float inv = 1.f / fmaxf((float)(e - b), 1.f);
        g_loopw[n] = s0 * inv;
        g_loopw[NN + n] = s1 * inv;
        g_loopw[2 * NN + n] = s2 * inv;
    }
}

// ---------------- fused GAT: online softmax + fp16 gather + bias + LN + residual + split out ----------------
#define GCH 128
__global__ __launch_bounds__(256) void k_gather(const float* __restrict__ x,
                                                float* __restrict__ xo,
                                                __half* __restrict__ xh,
                                                __half* __restrict__ xl,
                                                int l,
                                                const float* __restrict__ gat_b,
                                                const float* __restrict__ ln_g,
                                                const float* __restrict__ ln_b) {
    int n = blockIdx.x, tid = threadIdx.x;
    int lane = tid & 31, wid = tid >> 5;
    int head = tid >> 6, f4 = tid & 63;
    __shared__ int ssrc[GCH];
    __shared__ float slog[GCH][4];
    __shared__ float wt[GCH][4];
    __shared__ float sm4[4], ss4[4], sf4[4];
    __shared__ float sred[1024];
    __shared__ float sw[8];
    __shared__ float sMu, sVar;

    int beg = g_rowptr[n];
    int deg = g_rowptr[n + 1] - beg;

    float4 adv = *(const float4*)&g_ad[n * 4];
    float4 cv = *(const float4*)&g_cvec[l * 4];
    float lw = g_loopw[l * NN + n];
    if (tid < 4) {
        float sl = lrelu(g_as[n * 4 + tid] + g_ad[n * 4 + tid] + lw * g_cvec[l * 4 + tid]);
        sm4[tid] = sl;
        ss4[tid] = 1.f;
    }
    __syncthreads();

    const uint2* xp2 = (const uint2*)g_xph;   // 4 halfs per uint2
    size_t hb = (size_t)head * 64 + f4;       // uint2 index within row of 256 uint2
    float4 sv = h4tof4(xp2[(size_t)n * 256 + hb]);
    float4 acc = sv;   // self, weight 1 at current max

    for (int ch = 0; ch < deg; ch += GCH) {
        int cnt = min(GCH, deg - ch);
        if (tid < cnt) {
            int p = beg + ch + tid;
            int s0 = g_csrc[p];
            float w = g_ew[l * EE + g_ceid[p]];
            ssrc[tid] = s0;
            float4 as4 = *(const float4*)&g_as[s0 * 4];
            slog[tid][0] = lrelu(as4.x + adv.x + w * cv.x);
            slog[tid][1] = lrelu(as4.y + adv.y + w * cv.y);
            slog[tid][2] = lrelu(as4.z + adv.z + w * cv.z);
            slog[tid][3] = lrelu(as4.w + adv.w + w * cv.w);
        }
        __syncthreads();
        if (wid < 4) {
            int h = wid;
            float cm = -1e30f;
            for (int j = lane; j < cnt; j += 32) cm = fmaxf(cm, slog[j][h]);
            for (int o = 16; o; o >>= 1) cm = fmaxf(cm, __shfl_xor_sync(0xffffffff, cm, o));
            float mold = sm4[h];
            float mnew = fmaxf(mold, cm);
            float fac = expf(mold - mnew);
            float cs = 0.f;
            for (int j = lane; j < cnt; j += 32) {
                float p = expf(slog[j][h] - mnew);
                wt[j][h] = p;
                cs += p;
            }
            for (int o = 16; o; o >>= 1) cs += __shfl_xor_sync(0xffffffff, cs, o);
            if (lane == 0) {
                ss4[h] = ss4[h] * fac + cs;
                sm4[h] = mnew;
                sf4[h] = fac;
            }
        }
        __syncthreads();
        float f = sf4[head];
        acc.x *= f; acc.y *= f; acc.z *= f; acc.w *= f;
        int j = 0;
        for (; j + 4 <= cnt; j += 4) {
            float a0 = wt[j][head], a1 = wt[j + 1][head];
            float a2 = wt[j + 2][head], a3 = wt[j + 3][head];
            float4 v0 = h4tof4(xp2[(size_t)ssrc[j] * 256 + hb]);
            float4 v1 = h4tof4(xp2[(size_t)ssrc[j + 1] * 256 + hb]);
            float4 v2 = h4tof4(xp2[(size_t)ssrc[j + 2] * 256 + hb]);
            float4 v3 = h4tof4(xp2[(size_t)ssrc[j + 3] * 256 + hb]);
            acc.x += a0 * v0.x + a1 * v1.x + a2 * v2.x + a3 * v3.x;
            acc.y += a0 * v0.y + a1 * v1.y + a2 * v2.y + a3 * v3.y;
            acc.z += a0 * v0.z + a1 * v1.z + a2 * v2.z + a3 * v3.z;
            acc.w += a0 * v0.w + a1 * v1.w + a2 * v2.w + a3 * v3.w;
        }
        for (; j < cnt; j++) {
            float a = wt[j][head];
            float4 v = h4tof4(xp2[(size_t)ssrc[j] * 256 + hb]);
            acc.x += a * v.x;
            acc.y += a * v.y;
            acc.z += a * v.z;
            acc.w += a * v.w;
        }
        __syncthreads();   // before smem reuse next chunk
    }

    float inv = 0.25f / ss4[head];
    acc.x *= inv; acc.y *= inv; acc.z *= inv; acc.w *= inv;
    *(float4*)&sred[head * 256 + f4 * 4] = acc;
    __syncthreads();

    float h = sred[tid] + sred[256 + tid] + sred[512 + tid] + sred[768 + tid] + gat_b[tid];

    float v = h;
    for (int o = 16; o; o >>= 1) v += __shfl_xor_sync(0xffffffff, v, o);
    if (lane == 0) sw[wid] = v;
    __syncthreads();
    if (tid == 0) {
        float t = sw[0] + sw[1] + sw[2] + sw[3] + sw[4] + sw[5] + sw[6] + sw[7];
        sMu = t * (1.f / 256.f);
    }
    __syncthreads();
    float mu = sMu;
    float df = h - mu;
    v = df * df;
    for (int o = 16; o; o >>= 1) v += __shfl_xor_sync(0xffffffff, v, o);
    __syncthreads();
    if (lane == 0) sw[wid] = v;
    __syncthreads();
    if (tid == 0) {
        float t = sw[0] + sw[1] + sw[2] + sw[3] + sw[4] + sw[5] + sw[6] + sw[7];
        sVar = t * (1.f / 256.f);
    }
    __syncthreads();
    float y = ln_g[tid] * df * rsqrtf(sVar + 1e-5f) + ln_b[tid];
    size_t idx = (size_t)n * 256 + tid;
    float o = fmaxf(x[idx] + y, 0.f);
    xo[idx] = o;
    __half hh = __float2half(o);
    xh[idx] = hh;
    xl[idx] = __float2half(o - __half2float(hh));
}

// ---------------- prediction heads epilogue ----------------
__global__ void k_headout(const float* __restrict__ w2, const float* __restrict__ b2,
                          float* __restrict__ out) {
    int n = blockIdx.x;
    int k = threadIdx.x >> 5, lane = threadIdx.x & 31;
    const float* hr = g_hmid + (size_t)n * 512 + k * 128;
    const float* w = w2 + k * 128;
    float s = 0.f;
    for (int i = lane; i < 128; i += 32) s += hr[i] * w[i];
    for (int o = 16; o; o >>= 1) s += __shfl_down_sync(0xffffffff, s, o);
    if (lane == 0) {
        float v = s + b2[k];
        if (k == 0 || k == 3) v = 1.f / (1.f + expf(-v));
        out[(size_t)k * NN + n] = v;
    }
}

// ---------------- launch ----------------
extern "C" void kernel_launch(void* const* d_in, const int* in_sizes, int n_in,
                              void* d_out, int out_size) {
    const float* node_features = (const float*)d_in[0];
    const float* edge_attr     = (const float*)d_in[1];
    const float* enc_w         = (const float*)d_in[2];
    const float* enc_b         = (const float*)d_in[3];
    const float* edge_enc_w    = (const float*)d_in[4];
    const float* edge_enc_b    = (const float*)d_in[5];
    const float* gat_w         = (const float*)d_in[6];
    const float* att_src       = (const float*)d_in[7];
    const float* att_dst       = (const float*)d_in[8];
    const float* att_edge      = (const float*)d_in[9];
    const float* lin_edge_w    = (const float*)d_in[10];
    const float* gat_b         = (const float*)d_in[11];
    const float* ln_g          = (const float*)d_in[12];
    const float* ln_b          = (const float*)d_in[13];
    const float* head_w1       = (const float*)d_in[14];
    const float* head_b1       = (const float*)d_in[15];
    const float* head_w2       = (const float*)d_in[16];
    const float* head_b2       = (const float*)d_in[17];
    const int*   src           = (const int*)d_in[18];
    const int*   dst           = src + EE;
    float* out = (float*)d_out;

    float *px, *px2, *phmid;
    __half *pxph, *pAh, *pAl, *pXh, *pXl, *pBh, *pBl;
    cudaGetSymbolAddress((void**)&px, g_x);
    cudaGetSymbolAddress((void**)&px2, g_x2);
    cudaGetSymbolAddress((void**)&pxph, g_xph);
    cudaGetSymbolAddress((void**)&phmid, g_hmid);
    cudaGetSymbolAddress((void**)&pAh, g_Ah);
    cudaGetSymbolAddress((void**)&pAl, g_Al);
    cudaGetSymbolAddress((void**)&pXh, g_Xh);
    cudaGetSymbolAddress((void**)&pXl, g_Xl);
    cudaGetSymbolAddress((void**)&pBh, g_Bh);
    cudaGetSymbolAddress((void**)&pBl, g_Bl);

    cudaFuncSetAttribute(k_mma, cudaFuncAttributeMaxDynamicSharedMemorySize, GEMM_SMEM);

    const int MT = (NN + 127) / 128;  // 157 M-tiles

    // ---- graph preprocessing (dst-CSR) + per-layer constants ----
    k_zero<<<(NN + 255) / 256, 256>>>();
    k_count<<<(EE + 255) / 256, 256>>>(dst);
    k_scan<<<1, 1024>>>();
    k_scatter<<<(EE + 255) / 256, 256>>>(src, dst);
    k_wmean<<<NL * EDIM, 256>>>(edge_enc_w);
    k_bmean<<<NL, 256>>>(edge_enc_b);
    k_cvec<<<NL * NHEADS, 256>>>(lin_edge_w, att_edge);
    k_ew3<<<(EE + 7) / 8, 256>>>(edge_attr);
    k_loopw3<<<(NN + 255) / 256, 256>>>();

    // ---- encoder: x = relu(nf @ enc_w + enc_b) -> fp32 x + fp16 hi/lo split ----
    k_cvtA<<<(NN * NDIM + 255) / 256, 256>>>(node_features, pAh, pAl, NN * NDIM);
    k_cvtBT<<<(NDIM * HD + 255) / 256, 256>>>(enc_w, pBh, pBl, NDIM, HD);
    k_mma<<<dim3(HD / 128, MT), 256, GEMM_SMEM>>>(pAh, pAl, pBh, pBl,
                                                  px, nullptr, pXh, pXl,
                                                  NN, HD, NDIM, enc_b, 1, nullptr, nullptr);

    // ---- 3 GAT layers ----
    for (int l = 0; l < NL; l++) {
        const float* A = (l & 1) ? px2 : px;
        float* XO      = (l == 2) ? out + 4 * NN : ((l & 1) ? px : px2);

        // xp = x @ gat_w[l] -> fp16 xp; a_s/a_d fused into epilogue
        k_zeroAS<<<(NN * 4 + 255) / 256, 256>>>();
        k_cvtBT<<<(HD * 1024 + 255) / 256, 256>>>(gat_w + (size_t)l * 256 * 1024,
                                                  pBh, pBl, HD, 1024);
        k_mma<<<dim3(1024 / 128, MT), 256, GEMM_SMEM>>>(pXh, pXl, pBh, pBl,
                                                        nullptr, pxph, nullptr, nullptr,
                                                        NN, 1024, HD, nullptr, 0,
                                                        att_src + l * 1024, att_dst + l * 1024);

        k_gather<<<NN, 256>>>(A, XO, pXh, pXl, l,
                              gat_b + l * 256, ln_g + l * 256, ln_b + l * 256);
    }
    // emb now lives directly in out[4*NN ..]; fp16 hi/lo split in pXh/pXl

    // ---- combined prediction heads: hmid = relu(emb @ [W1_0|W1_1|W1_2|W1_3] + b1) ----
    k_cvtHW<<<(512 * 256 + 255) / 256, 256>>>(head_w1, pBh, pBl);
    k_mma<<<dim3(512 / 128, MT), 256, GEMM_SMEM>>>(pXh, pXl, pBh, pBl,
                                                   phmid, nullptr, nullptr, nullptr,
                                                   NN, 512, HD, head_b1, 1, nullptr, nullptr);
    k_headout<<<NN, 128>>>(head_w2, head_b2, out);
}